// round 9
// baseline (speedup 1.0000x reference)
#include <cuda_runtime.h>
#include <cuda_bf16.h>
#include <math.h>
#include <stdint.h>

// Problem constants
#define B_SZ 2
#define T_SZ 2048
#define C_SZ 2048
#define NH 32
#define NKV 8
#define HD 64
#define ROWS (B_SZ * T_SZ)          // 4096
#define QKVLD 3072                  // fused qkv row stride

typedef __nv_bfloat16 bf16;

// int8 limb scales (bounds: |x| <= 6.0, |W| <= 0.12; limb range ±32639)
#define S_ACT 5439.0f               // 32639 / 6.0
#define S_WGT 271990.0f             // 32639 / 0.12
#define QCLIP 32639.0f

// Scratch (allocation-free: __device__ globals)
__device__ float g_qkv[ROWS * QKVLD];
__device__ float g_y[ROWS * C_SZ];

__device__ char g_xh8[ROWS * C_SZ], g_xl8[ROWS * C_SZ];
__device__ char g_wh8[QKVLD * C_SZ], g_wl8[QKVLD * C_SZ];   // [Wq|Wk|Wv]^T limbs
__device__ bf16 g_yh[ROWS * C_SZ], g_yl[ROWS * C_SZ];
__device__ bf16 g_woh[C_SZ * C_SZ], g_wol[C_SZ * C_SZ];     // Wo^T bf16 planes

// ---------------------------------------------------------------------------
#define CP_ASYNC16(dst, src) \
    asm volatile("cp.async.cg.shared.global [%0], [%1], 16;\n" :: "r"(dst), "l"(src))

__device__ __forceinline__ unsigned cvt_tf32(float f) {
    unsigned u;
    asm("cvt.rna.tf32.f32 %0, %1;" : "=r"(u) : "f"(f));
    return u;
}

__device__ __forceinline__ uint32_t smem_u32(const void* p) {
    uint32_t a;
    asm("{ .reg .u64 t; cvta.to.shared.u64 t, %1; cvt.u32.u64 %0, t; }" : "=r"(a) : "l"(p));
    return a;
}

#define MMA_TF32(d, a, b) \
    asm volatile("mma.sync.aligned.m16n8k8.row.col.f32.tf32.tf32.f32 " \
                 "{%0,%1,%2,%3}, {%4,%5,%6,%7}, {%8,%9}, {%0,%1,%2,%3};\n" \
                 : "+f"(d[0]), "+f"(d[1]), "+f"(d[2]), "+f"(d[3]) \
                 : "r"(a[0]), "r"(a[1]), "r"(a[2]), "r"(a[3]), "r"(b[0]), "r"(b[1]))

#define MMA_S8(d, a, b) \
    asm volatile("mma.sync.aligned.m16n8k32.row.col.s32.s8.s8.s32 " \
                 "{%0,%1,%2,%3}, {%4,%5,%6,%7}, {%8,%9}, {%0,%1,%2,%3};\n" \
                 : "+r"(d[0]), "+r"(d[1]), "+r"(d[2]), "+r"(d[3]) \
                 : "r"(a[0]), "r"(a[1]), "r"(a[2]), "r"(a[3]), "r"(b[0]), "r"(b[1]))

#define MMA_BF16(d, a, b) \
    asm volatile("mma.sync.aligned.m16n8k16.row.col.f32.bf16.bf16.f32 " \
                 "{%0,%1,%2,%3}, {%4,%5,%6,%7}, {%8,%9}, {%0,%1,%2,%3};\n" \
                 : "+f"(d[0]), "+f"(d[1]), "+f"(d[2]), "+f"(d[3]) \
                 : "r"(a[0]), "r"(a[1]), "r"(a[2]), "r"(a[3]), "r"(b[0]), "r"(b[1]))

// ---------------------------------------------------------------------------
// Quantize fp32 -> 2-limb int8 (X = h*256 + l exact)
// ---------------------------------------------------------------------------
__global__ void q8_kernel(const float* __restrict__ x, char* __restrict__ h,
                          char* __restrict__ l, int n, float S) {
    int i = blockIdx.x * blockDim.x + threadIdx.x;
    if (i >= n) return;
    float v = fminf(fmaxf(x[i] * S, -QCLIP), QCLIP);
    int X = __float2int_rn(v);
    int hh = (X + 128) >> 8;
    int ll = X - (hh << 8);
    h[i] = (char)hh;
    l[i] = (char)ll;
}

// ---------------------------------------------------------------------------
// Transpose + quantize fused QKV weights -> limbs [3072][2048]
// ---------------------------------------------------------------------------
__global__ void tq8_qkv(const float* __restrict__ Wq, const float* __restrict__ Wk,
                        const float* __restrict__ Wv, char* __restrict__ h,
                        char* __restrict__ l) {
    __shared__ float s[32][33];
    int tx = threadIdx.x, ty = threadIdx.y;     // 32 x 8
    int bx = blockIdx.x, gk = blockIdx.y * 32;
    const float* W;
    int N, nb, obase;
    if (bx < 64)      { W = Wq; N = 2048; nb = bx;      obase = 0; }
    else if (bx < 80) { W = Wk; N = 512;  nb = bx - 64; obase = 2048; }
    else              { W = Wv; N = 512;  nb = bx - 80; obase = 2560; }
    int gn = nb * 32;
#pragma unroll
    for (int j = 0; j < 4; j++)
        s[ty + j * 8][tx] = W[(size_t)(gk + ty + j * 8) * N + gn + tx];
    __syncthreads();
#pragma unroll
    for (int j = 0; j < 4; j++) {
        float v = fminf(fmaxf(s[tx][ty + j * 8] * S_WGT, -QCLIP), QCLIP);
        int X = __float2int_rn(v);
        int hh = (X + 128) >> 8;
        int ll = X - (hh << 8);
        size_t o = (size_t)(obase + gn + ty + j * 8) * C_SZ + gk + tx;
        h[o] = (char)hh;
        l[o] = (char)ll;
    }
}

// ---------------------------------------------------------------------------
// Transpose + bf16 split: Wo [K][N] fp32 -> hi/lo [N][K] bf16
// ---------------------------------------------------------------------------
__global__ void tsplit_kernel(const float* __restrict__ W, bf16* __restrict__ hi,
                              bf16* __restrict__ lo, int K, int N) {
    __shared__ float s[32][33];
    int tx = threadIdx.x, ty = threadIdx.y;     // 32 x 8
    int gn = blockIdx.x * 32, gk = blockIdx.y * 32;
#pragma unroll
    for (int j = 0; j < 4; j++)
        s[ty + j * 8][tx] = W[(size_t)(gk + ty + j * 8) * N + gn + tx];
    __syncthreads();
#pragma unroll
    for (int j = 0; j < 4; j++) {
        float v = s[tx][ty + j * 8];
        bf16 h = __float2bfloat16(v);
        size_t o = (size_t)(gn + ty + j * 8) * K + gk + tx;
        hi[o] = h;
        lo[o] = __float2bfloat16(v - __bfloat162float(h));
    }
}

// Elementwise fp32 -> bf16 hi/lo split (for y)
__global__ void split_kernel(const float* __restrict__ x, bf16* __restrict__ hi,
                             bf16* __restrict__ lo, int n) {
    int i = blockIdx.x * blockDim.x + threadIdx.x;
    if (i >= n) return;
    float v = x[i];
    bf16 h = __float2bfloat16(v);
    hi[i] = h;
    lo[i] = __float2bfloat16(v - __bfloat162float(h));
}

// ---------------------------------------------------------------------------
// int8 4-product limb GEMM (QKV projection): C = A @ Bt^T
// CTA 128x128, BK=64B, 512 threads, 2-stage cp.async. Row stride 80B.
// ---------------------------------------------------------------------------
#define IBM 128
#define IBN 128
#define IBK 64
#define ISTR 80
#define IPLANE (128 * ISTR)
#define ISTAGE (4 * IPLANE)         // 40960
#define IWRD 20
#define IR8 160

__global__ __launch_bounds__(512, 1) void gemm_i8(const char* __restrict__ Ah,
                                                  const char* __restrict__ Al,
                                                  const char* __restrict__ Bh,
                                                  const char* __restrict__ Bl,
                                                  float* __restrict__ C,
                                                  int M, int N, int K, float invSS) {
    extern __shared__ char sm8[];
    int tid = threadIdx.x, w = tid >> 5, lane = tid & 31;
    int g = lane >> 2, tg = lane & 3;
    int wm = (w & 3) * 32, wn = (w >> 2) * 32;
    int brow = blockIdx.y * IBM, bcol = blockIdx.x * IBN;

    int accH[2][4][4] = {};
    int accX[2][4][4] = {};
    int accL[2][4][4] = {};

    const char* pb[4] = { Ah + (size_t)brow * K, Al + (size_t)brow * K,
                          Bh + (size_t)bcol * K, Bl + (size_t)bcol * K };

    auto fill = [&](int t, int s) {
        char* stg = sm8 + s * ISTAGE;
#pragma unroll
        for (int i = 0; i < 4; i++) {
            int idx = tid + i * 512;
            int plane = idx >> 9;
            int rem = idx & 511;
            int row = rem >> 2, ch = rem & 3;
            const char* src = pb[plane] + (size_t)row * K + t * IBK + ch * 16;
            unsigned d = smem_u32(stg + plane * IPLANE + row * ISTR + ch * 16);
            CP_ASYNC16(d, src);
        }
        asm volatile("cp.async.commit_group;\n");
    };

    const int nT = K / IBK;   // 32
    fill(0, 0);
    fill(1, 1);
    asm volatile("cp.async.wait_group 1;\n");
    __syncthreads();

    for (int t = 0; t < nT; t++) {
        int s = t & 1;
        const int* base = (const int*)(sm8 + s * ISTAGE);
        const int* ah = base;
        const int* al = base + IPLANE / 4;
        const int* bh = base + 2 * IPLANE / 4;
        const int* bl = base + 3 * IPLANE / 4;

#pragma unroll
        for (int ks = 0; ks < 2; ks++) {
            int kw = ks * 8 + tg;
            int Af[2][4], Lf[2][4];
#pragma unroll
            for (int mt = 0; mt < 2; mt++) {
                const int* p = ah + (wm + mt * 16 + g) * IWRD + kw;
                Af[mt][0] = p[0];  Af[mt][1] = p[IR8];
                Af[mt][2] = p[4];  Af[mt][3] = p[IR8 + 4];
                const int* q = al + (wm + mt * 16 + g) * IWRD + kw;
                Lf[mt][0] = q[0];  Lf[mt][1] = q[IR8];
                Lf[mt][2] = q[4];  Lf[mt][3] = q[IR8 + 4];
            }
#pragma unroll
            for (int nt = 0; nt < 4; nt++) {
                int Bf[2], Bg[2];
                const int* p = bh + (wn + nt * 8 + g) * IWRD + kw;
                Bf[0] = p[0];  Bf[1] = p[4];
                const int* q = bl + (wn + nt * 8 + g) * IWRD + kw;
                Bg[0] = q[0];  Bg[1] = q[4];
#pragma unroll
                for (int mt = 0; mt < 2; mt++) {
                    MMA_S8(accH[mt][nt], Af[mt], Bf);
                    MMA_S8(accX[mt][nt], Af[mt], Bg);
                    MMA_S8(accX[mt][nt], Lf[mt], Bf);
                    MMA_S8(accL[mt][nt], Lf[mt], Bg);
                }
            }
        }
        __syncthreads();
        if (t + 2 < nT) fill(t + 2, s);
        if (t + 1 < nT) {
            asm volatile("cp.async.wait_group %0;\n" :: "n"(1));
            __syncthreads();
        }
    }

#pragma unroll
    for (int mt = 0; mt < 2; mt++) {
        int r0 = brow + wm + mt * 16 + g;
#pragma unroll
        for (int nt = 0; nt < 4; nt++) {
            int c0 = bcol + wn + nt * 8 + tg * 2;
            float v0 = ((float)accH[mt][nt][0] * 65536.0f + (float)accX[mt][nt][0] * 256.0f
                        + (float)accL[mt][nt][0]) * invSS;
            float v1 = ((float)accH[mt][nt][1] * 65536.0f + (float)accX[mt][nt][1] * 256.0f
                        + (float)accL[mt][nt][1]) * invSS;
            float v2 = ((float)accH[mt][nt][2] * 65536.0f + (float)accX[mt][nt][2] * 256.0f
                        + (float)accL[mt][nt][2]) * invSS;
            float v3 = ((float)accH[mt][nt][3] * 65536.0f + (float)accX[mt][nt][3] * 256.0f
                        + (float)accL[mt][nt][3]) * invSS;
            *(float2*)&C[(size_t)r0 * N + c0] = make_float2(v0, v1);
            *(float2*)&C[(size_t)(r0 + 8) * N + c0] = make_float2(v2, v3);
        }
    }
}

// ---------------------------------------------------------------------------
// bf16x3 tensor-core GEMM (Wo projection) — R4 passing version
// ---------------------------------------------------------------------------
#define BBM 128
#define BBN 128
#define BBK 32
#define KSTR 40
#define BPLANE (128 * KSTR)
#define BPLANE32 (BPLANE / 2)

__global__ __launch_bounds__(256) void gemm_b3(const bf16* __restrict__ Ah,
                                               const bf16* __restrict__ Al,
                                               const bf16* __restrict__ Bh,
                                               const bf16* __restrict__ Bl,
                                               float* __restrict__ C,
                                               int M, int N, int K) {
    extern __shared__ bf16 smb[];

    int tid = threadIdx.x;
    int warp = tid >> 5, lane = tid & 31;
    int g = lane >> 2, tg = lane & 3;
    int wm = (warp & 1) * 64;
    int wn = (warp >> 1) * 32;
    int brow = blockIdx.y * BBM, bcol = blockIdx.x * BBN;

    float acc[4][4][4] = {};
    const int nK = K / BBK;

    auto loadTile = [&](int kt, int buf) {
        bf16* dstb = smb + buf * (4 * BPLANE);
#pragma unroll
        for (int i = 0; i < 8; i++) {
            int idx = tid + i * 256;
            int plane = idx >> 9;
            int rem = idx & 511;
            int row = rem >> 2, c = rem & 3;
            const bf16* src;
            if (plane == 0)      src = Ah + (size_t)(brow + row) * K;
            else if (plane == 1) src = Al + (size_t)(brow + row) * K;
            else if (plane == 2) src = Bh + (size_t)(bcol + row) * K;
            else                 src = Bl + (size_t)(bcol + row) * K;
            src += kt * BBK + c * 8;
            unsigned d = smem_u32(dstb + plane * BPLANE + row * KSTR + c * 8);
            CP_ASYNC16(d, src);
        }
        asm volatile("cp.async.commit_group;\n");
    };

    loadTile(0, 0);

    for (int kt = 0; kt < nK; kt++) {
        if (kt + 1 < nK) {
            loadTile(kt + 1, (kt + 1) & 1);
            asm volatile("cp.async.wait_group 1;\n");
        } else {
            asm volatile("cp.async.wait_group 0;\n");
        }
        __syncthreads();

        const unsigned* ah = (const unsigned*)(smb + (kt & 1) * (4 * BPLANE));
        const unsigned* al = ah + BPLANE32;
        const unsigned* bh = ah + 2 * BPLANE32;
        const unsigned* bl = ah + 3 * BPLANE32;

#pragma unroll
        for (int ks = 0; ks < 2; ks++) {
            int kc = ks * 8 + tg;
            unsigned Afh[4][4], Afl[4][4], Bfh[4][2], Bfl[4][2];
#pragma unroll
            for (int mt = 0; mt < 4; mt++) {
                int o = (wm + mt * 16 + g) * 20 + kc;
                Afh[mt][0] = ah[o];       Afh[mt][1] = ah[o + 160];
                Afh[mt][2] = ah[o + 4];   Afh[mt][3] = ah[o + 164];
                Afl[mt][0] = al[o];       Afl[mt][1] = al[o + 160];
                Afl[mt][2] = al[o + 4];   Afl[mt][3] = al[o + 164];
            }
#pragma unroll
            for (int nt = 0; nt < 4; nt++) {
                int o = (wn + nt * 8 + g) * 20 + kc;
                Bfh[nt][0] = bh[o];  Bfh[nt][1] = bh[o + 4];
                Bfl[nt][0] = bl[o];  Bfl[nt][1] = bl[o + 4];
            }
#pragma unroll
            for (int mt = 0; mt < 4; mt++)
#pragma unroll
                for (int nt = 0; nt < 4; nt++) {
                    MMA_BF16(acc[mt][nt], Afh[mt], Bfh[nt]);
                    MMA_BF16(acc[mt][nt], Afh[mt], Bfl[nt]);
                    MMA_BF16(acc[mt][nt], Afl[mt], Bfh[nt]);
                }
        }
        __syncthreads();
    }

#pragma unroll
    for (int mt = 0; mt < 4; mt++) {
        int r0 = brow + wm + mt * 16 + g;
#pragma unroll
        for (int nt = 0; nt < 4; nt++) {
            int c0 = bcol + wn + nt * 8 + tg * 2;
            *(float2*)&C[(size_t)r0 * N + c0] = make_float2(acc[mt][nt][0], acc[mt][nt][1]);
            *(float2*)&C[(size_t)(r0 + 8) * N + c0] = make_float2(acc[mt][nt][2], acc[mt][nt][3]);
        }
    }
}

// ---------------------------------------------------------------------------
// Fused RoPE + tf32-rna rounding over packed QKV.
// 48 slots: 0-31 q rope (fp32), 32-39 k rope+rna, 40-47 v rna only.
// ---------------------------------------------------------------------------
__global__ void rope_fused(float* __restrict__ qkv) {
    int idx = blockIdx.x * blockDim.x + threadIdx.x;
    int total = ROWS * 48 * 32;
    if (idx >= total) return;
    int i = idx & 31;
    int hh = (idx >> 5) % 48;
    int row = idx / (48 * 32);

    float* p;
    if (hh < 32)      p = qkv + (size_t)row * QKVLD + hh * HD;
    else if (hh < 40) p = qkv + (size_t)row * QKVLD + 2048 + (hh - 32) * HD;
    else              p = qkv + (size_t)row * QKVLD + 2560 + (hh - 40) * HD;

    if (hh >= 40) {   // v: round to tf32-rna only
        p[i]      = __uint_as_float(cvt_tf32(p[i]));
        p[i + 32] = __uint_as_float(cvt_tf32(p[i + 32]));
        return;
    }

    int t = row & (T_SZ - 1);
    float invf = expf(-(float)i * 0.28782313662425574f);  // ln(10000)/32
    float ang = (float)t * invf;
    float c = cosf(ang), s = sinf(ang);

    float x0 = p[i];
    float x1 = p[i + 32];
    float r0 = x0 * c - x1 * s;
    float r1 = x1 * c + x0 * s;
    if (hh >= 32) {   // k: rope + rna round
        p[i]      = __uint_as_float(cvt_tf32(r0));
        p[i + 32] = __uint_as_float(cvt_tf32(r1));
    } else {          // q: rope, fp32 (rna happens in flash)
        p[i]      = r0;
        p[i + 32] = r1;
    }
}

// ---------------------------------------------------------------------------
// TF32 tensor-core flash attention (causal) — fused-QKV layout (stride 3072)
// ---------------------------------------------------------------------------
#define FQ 128
#define FK 64
#define FSTR 68
#define FBUF (FK * FSTR * 2)

__global__ __launch_bounds__(256, 2) void flash_tc(const float* __restrict__ qkv,
                                                   float* __restrict__ y) {
    extern __shared__ float smf[];
    int qt = blockIdx.x, h = blockIdx.y, b = blockIdx.z;
    int hk = h >> 2;
    int tid = threadIdx.x, w = tid >> 5, lane = tid & 31;
    int g = lane >> 2, tg = lane & 3;
    int qbase = qt * FQ;
    size_t bT = (size_t)b * T_SZ;

    {
        const float* qg = qkv + (bT + qbase) * QKVLD + h * HD;
#pragma unroll
        for (int i = 0; i < 8; i++) {
            int idx = tid + i * 256;
            int r = idx >> 4, c4 = (idx & 15) * 4;
            unsigned d = smem_u32(smf + r * FSTR + c4);
            CP_ASYNC16(d, qg + (size_t)r * QKVLD + c4);
        }
        asm volatile("cp.async.commit_group;\ncp.async.wait_group 0;\n");
    }
    __syncthreads();

    unsigned qa[8][4];
    {
        int r0 = w * 16 + g;
#pragma unroll
        for (int c = 0; c < 8; c++) {
            qa[c][0] = cvt_tf32(smf[r0 * FSTR + 8 * c + tg] * 0.125f);
            qa[c][1] = cvt_tf32(smf[(r0 + 8) * FSTR + 8 * c + tg] * 0.125f);
            qa[c][2] = cvt_tf32(smf[r0 * FSTR + 8 * c + tg + 4] * 0.125f);
            qa[c][3] = cvt_tf32(smf[(r0 + 8) * FSTR + 8 * c + tg + 4] * 0.125f);
        }
    }
    __syncthreads();

    auto loadKV = [&](int kt, int buf) {
        float* base = smf + buf * FBUF;
        const float* kg = qkv + (bT + kt * FK) * QKVLD + 2048 + hk * HD;
        const float* vg = qkv + (bT + kt * FK) * QKVLD + 2560 + hk * HD;
#pragma unroll
        for (int i = 0; i < 4; i++) {
            int idx = tid + i * 256;
            int r = idx >> 4, c4 = (idx & 15) * 4;
            unsigned dk = smem_u32(base + r * FSTR + c4);
            CP_ASYNC16(dk, kg + (size_t)r * QKVLD + c4);
            unsigned dv = smem_u32(base + FK * FSTR + r * FSTR + c4);
            CP_ASYNC16(dv, vg + (size_t)r * QKVLD + c4);
        }
        asm volatile("cp.async.commit_group;\n");
    };

    float yacc[8][4] = {};
    float m0 = -INFINITY, m1 = -INFINITY, l0 = 0.0f, l1 = 0.0f;
    int rg0 = qbase + w * 16 + g;

    int nkt = 2 * qt + 2;
    loadKV(0, 0);

    for (int kt = 0; kt < nkt; kt++) {
        if (kt + 1 < nkt) {
            loadKV(kt + 1, (kt + 1) & 1);
            asm volatile("cp.async.wait_group 1;\n");
        } else {
            asm volatile("cp.async.wait_group 0;\n");
        }
        __syncthreads();

        bool active = (FK * kt <= qbase + 16 * w + 15);
        if (active) {
            const float* Ks = smf + (kt & 1) * FBUF;
            const float* Vs = Ks + FK * FSTR;

            float sacc[8][4] = {};
#pragma unroll
            for (int c = 0; c < 8; c++) {
#pragma unroll
                for (int nf = 0; nf < 8; nf++) {
                    unsigned bb[2];
                    bb[0] = __float_as_uint(Ks[(8 * nf + g) * FSTR + 8 * c + tg]);
                    bb[1] = __float_as_uint(Ks[(8 * nf + g) * FSTR + 8 * c + tg + 4]);
                    MMA_TF32(sacc[nf], qa[c], bb);
                }
            }

            if (kt >= 2 * qt) {
                int k0 = FK * kt;
#pragma unroll
                for (int nf = 0; nf < 8; nf++) {
                    int jg = k0 + 8 * nf + 2 * tg;
                    if (jg > rg0)     sacc[nf][0] = -INFINITY;
                    if (jg + 1 > rg0) sacc[nf][1] = -INFINITY;
                    if (jg > rg0 + 8)     sacc[nf][2] = -INFINITY;
                    if (jg + 1 > rg0 + 8) sacc[nf][3] = -INFINITY;
                }
            }

            float mt0 = -INFINITY, mt1 = -INFINITY;
#pragma unroll
            for (int nf = 0; nf < 8; nf++) {
                mt0 = fmaxf(mt0, fmaxf(sacc[nf][0], sacc[nf][1]));
                mt1 = fmaxf(mt1, fmaxf(sacc[nf][2], sacc[nf][3]));
            }
            mt0 = fmaxf(mt0, __shfl_xor_sync(0xffffffffu, mt0, 1));
            mt0 = fmaxf(mt0, __shfl_xor_sync(0xffffffffu, mt0, 2));
            mt1 = fmaxf(mt1, __shfl_xor_sync(0xffffffffu, mt1, 1));
            mt1 = fmaxf(mt1, __shfl_xor_sync(0xffffffffu, mt1, 2));

            float mn0 = fmaxf(m0, mt0), mn1 = fmaxf(m1, mt1);
            float al0 = __expf(m0 - mn0), al1 = __expf(m1 - mn1);
            m0 = mn0; m1 = mn1;
#pragma unroll
            for (int nf = 0; nf < 8; nf++) {
                yacc[nf][0] *= al0; yacc[nf][1] *= al0;
                yacc[nf][2] *= al1; yacc[nf][3] *= al1;
            }

            float pl0 = 0.0f, pl1 = 0.0f;
#pragma unroll
            for (int c = 0; c < 8; c++) {
                float p0 = __expf(sacc[c][0] - mn0);
                float p1 = __expf(sacc[c][1] - mn0);
                float p2 = __expf(sacc[c][2] - mn1);
                float p3 = __expf(sacc[c][3] - mn1);
                pl0 += p0 + p1;
                pl1 += p2 + p3;
                unsigned pa[4];
                pa[0] = cvt_tf32(p0);
                pa[1] = cvt_tf32(p2);
                pa[2] = cvt_tf32(p1);
                pa[3] = cvt_tf32(p3);
#pragma unroll
                for (int nf = 0; nf < 8; nf++) {
                    unsigned bb[2];
                    bb[0] = __float_as_uint(Vs[(8 * c + 2 * tg) * FSTR + 8 * nf + g]);
                    bb[1] = __float_as_uint(Vs[(8 * c + 2 * tg + 1) * FSTR + 8 * nf + g]);
                    MMA_TF32(yacc[nf], pa, bb);
                }
            }
            pl0 += __shfl_xor_sync(0xffffffffu, pl0, 1);
            pl0 += __shfl_xor_sync(0xffffffffu, pl0, 2);
            pl1 += __shfl_xor_sync(0xffffffffu, pl1, 1);
            pl1 += __shfl_xor_sync(0xffffffffu, pl1, 2);
            l0 = l0 * al0 + pl0;
            l1 = l1 * al1 + pl1;
        }
        __syncthreads();
    }

    float inv0 = 1.0f / l0, inv1 = 1.0f / l1;
    float* yo0 = y + (bT + qbase + w * 16 + g) * C_SZ + h * HD;
    float* yo1 = yo0 + 8 * C_SZ;
#pragma unroll
    for (int nf = 0; nf < 8; nf++) {
        *(float2*)&yo0[8 * nf + 2 * tg] = make_float2(yacc[nf][0] * inv0, yacc[nf][1] * inv0);
        *(float2*)&yo1[8 * nf + 2 * tg] = make_float2(yacc[nf][2] * inv1, yacc[nf][3] * inv1);
    }
}

// ---------------------------------------------------------------------------
extern "C" void kernel_launch(void* const* d_in, const int* in_sizes, int n_in,
                              void* d_out, int out_size) {
    const float* x  = (const float*)d_in[0];
    const float* Wq = (const float*)d_in[1];
    const float* Wk = (const float*)d_in[2];
    const float* Wv = (const float*)d_in[3];
    const float* Wo = (const float*)d_in[4];
    float* out = (float*)d_out;

    float *pqkv, *py;
    cudaGetSymbolAddress((void**)&pqkv, g_qkv);
    cudaGetSymbolAddress((void**)&py, g_y);

    char *xh, *xl, *wh, *wl;
    cudaGetSymbolAddress((void**)&xh, g_xh8); cudaGetSymbolAddress((void**)&xl, g_xl8);
    cudaGetSymbolAddress((void**)&wh, g_wh8); cudaGetSymbolAddress((void**)&wl, g_wl8);
    bf16 *yh, *yl, *woh, *wol;
    cudaGetSymbolAddress((void**)&yh, g_yh);  cudaGetSymbolAddress((void**)&yl, g_yl);
    cudaGetSymbolAddress((void**)&woh, g_woh); cudaGetSymbolAddress((void**)&wol, g_wol);

    int ismem = 2 * ISTAGE;                        // 81920
    cudaFuncSetAttribute(gemm_i8, cudaFuncAttributeMaxDynamicSharedMemorySize, ismem);
    int bsmem = 2 * 4 * BPLANE * (int)sizeof(bf16);// 81920
    cudaFuncSetAttribute(gemm_b3, cudaFuncAttributeMaxDynamicSharedMemorySize, bsmem);
    int fsmem = 2 * FBUF * (int)sizeof(float);     // 69632
    cudaFuncSetAttribute(flash_tc, cudaFuncAttributeMaxDynamicSharedMemorySize, fsmem);

    const float invSS = (float)(1.0 / ((double)S_ACT * (double)S_WGT));

    // (0) quantize x; (1) QKV weight limbs; (2) Wo bf16 planes
    {
        int n = ROWS * C_SZ;
        q8_kernel<<<(n + 255) / 256, 256>>>(x, xh, xl, n, S_ACT);
    }
    tq8_qkv<<<dim3(96, C_SZ / 32), dim3(32, 8)>>>(Wq, Wk, Wv, wh, wl);
    tsplit_kernel<<<dim3(C_SZ / 32, C_SZ / 32), dim3(32, 8)>>>(Wo, woh, wol, C_SZ, C_SZ);

    // (3) fused QKV projection (int8 limb IMMA)
    gemm_i8<<<dim3(QKVLD / IBN, ROWS / IBM), 512, ismem>>>(
        xh, xl, wh, wl, pqkv, ROWS, QKVLD, C_SZ, invSS);

    // (4) fused RoPE + k/v tf32-rna rounding
    {
        int tot = ROWS * 48 * 32;
        rope_fused<<<(tot + 255) / 256, 256>>>(pqkv);
    }

    // (5) flash attention (tf32)  <- ncu capture slot (-s 5)
    flash_tc<<<dim3(T_SZ / FQ, NH, B_SZ), 256, fsmem>>>(pqkv, py);

    // (6) split y, (7) output projection (bf16x3)
    {
        int n = ROWS * C_SZ;
        split_kernel<<<(n + 255) / 256, 256>>>(py, yh, yl, n);
        gemm_b3<<<dim3(C_SZ / BBN, ROWS / BBM), 256, bsmem>>>(
            yh, yl, woh, wol, out, ROWS, C_SZ, C_SZ);
    }
}

// round 11
// speedup vs baseline: 1.1512x; 1.1512x over previous
#include <cuda_runtime.h>
#include <cuda_bf16.h>
#include <math.h>
#include <stdint.h>

// Problem constants
#define B_SZ 2
#define T_SZ 2048
#define C_SZ 2048
#define NH 32
#define NKV 8
#define HD 64
#define ROWS (B_SZ * T_SZ)          // 4096
#define QKVLD 3072                  // fused qkv row stride

typedef __nv_bfloat16 bf16;

// int8 limb scales (bounds: |x| <= 6.0, |W| <= 0.12; limb range ±32639)
#define S_ACT 5439.0f
#define S_WGT 271990.0f
#define QCLIP 32639.0f

// Scratch (allocation-free: __device__ globals)
__device__ float g_qkv[ROWS * QKVLD];
__device__ float g_y[ROWS * C_SZ];

__device__ char g_xh8[ROWS * C_SZ], g_xl8[ROWS * C_SZ];
__device__ char g_wh8[QKVLD * C_SZ], g_wl8[QKVLD * C_SZ];   // [Wq|Wk|Wv]^T limbs
__device__ bf16 g_yh[ROWS * C_SZ], g_yl[ROWS * C_SZ];
__device__ bf16 g_woh[C_SZ * C_SZ], g_wol[C_SZ * C_SZ];     // Wo^T bf16 planes

// ---------------------------------------------------------------------------
#define CP_ASYNC16(dst, src) \
    asm volatile("cp.async.cg.shared.global [%0], [%1], 16;\n" :: "r"(dst), "l"(src))

__device__ __forceinline__ unsigned cvt_tf32(float f) {
    unsigned u;
    asm("cvt.rna.tf32.f32 %0, %1;" : "=r"(u) : "f"(f));
    return u;
}

__device__ __forceinline__ uint32_t smem_u32(const void* p) {
    uint32_t a;
    asm("{ .reg .u64 t; cvta.to.shared.u64 t, %1; cvt.u32.u64 %0, t; }" : "=r"(a) : "l"(p));
    return a;
}

#define MMA_TF32(d, a, b) \
    asm volatile("mma.sync.aligned.m16n8k8.row.col.f32.tf32.tf32.f32 " \
                 "{%0,%1,%2,%3}, {%4,%5,%6,%7}, {%8,%9}, {%0,%1,%2,%3};\n" \
                 : "+f"(d[0]), "+f"(d[1]), "+f"(d[2]), "+f"(d[3]) \
                 : "r"(a[0]), "r"(a[1]), "r"(a[2]), "r"(a[3]), "r"(b[0]), "r"(b[1]))

#define MMA_S8(d, a, b) \
    asm volatile("mma.sync.aligned.m16n8k32.row.col.s32.s8.s8.s32 " \
                 "{%0,%1,%2,%3}, {%4,%5,%6,%7}, {%8,%9}, {%0,%1,%2,%3};\n" \
                 : "+r"(d[0]), "+r"(d[1]), "+r"(d[2]), "+r"(d[3]) \
                 : "r"(a[0]), "r"(a[1]), "r"(a[2]), "r"(a[3]), "r"(b[0]), "r"(b[1]))

#define MMA_BF16(d, a, b) \
    asm volatile("mma.sync.aligned.m16n8k16.row.col.f32.bf16.bf16.f32 " \
                 "{%0,%1,%2,%3}, {%4,%5,%6,%7}, {%8,%9}, {%0,%1,%2,%3};\n" \
                 : "+f"(d[0]), "+f"(d[1]), "+f"(d[2]), "+f"(d[3]) \
                 : "r"(a[0]), "r"(a[1]), "r"(a[2]), "r"(a[3]), "r"(b[0]), "r"(b[1]))

// ---------------------------------------------------------------------------
// Quantize fp32 -> 2-limb int8 (X = h*256 + l exact)
// ---------------------------------------------------------------------------
__global__ void q8_kernel(const float* __restrict__ x, char* __restrict__ h,
                          char* __restrict__ l, int n, float S) {
    int i = blockIdx.x * blockDim.x + threadIdx.x;
    if (i >= n) return;
    float v = fminf(fmaxf(x[i] * S, -QCLIP), QCLIP);
    int X = __float2int_rn(v);
    int hh = (X + 128) >> 8;
    int ll = X - (hh << 8);
    h[i] = (char)hh;
    l[i] = (char)ll;
}

// ---------------------------------------------------------------------------
// Transpose + quantize fused QKV weights -> limbs [3072][2048]
// ---------------------------------------------------------------------------
__global__ void tq8_qkv(const float* __restrict__ Wq, const float* __restrict__ Wk,
                        const float* __restrict__ Wv, char* __restrict__ h,
                        char* __restrict__ l) {
    __shared__ float s[32][33];
    int tx = threadIdx.x, ty = threadIdx.y;     // 32 x 8
    int bx = blockIdx.x, gk = blockIdx.y * 32;
    const float* W;
    int N, nb, obase;
    if (bx < 64)      { W = Wq; N = 2048; nb = bx;      obase = 0; }
    else if (bx < 80) { W = Wk; N = 512;  nb = bx - 64; obase = 2048; }
    else              { W = Wv; N = 512;  nb = bx - 80; obase = 2560; }
    int gn = nb * 32;
#pragma unroll
    for (int j = 0; j < 4; j++)
        s[ty + j * 8][tx] = W[(size_t)(gk + ty + j * 8) * N + gn + tx];
    __syncthreads();
#pragma unroll
    for (int j = 0; j < 4; j++) {
        float v = fminf(fmaxf(s[tx][ty + j * 8] * S_WGT, -QCLIP), QCLIP);
        int X = __float2int_rn(v);
        int hh = (X + 128) >> 8;
        int ll = X - (hh << 8);
        size_t o = (size_t)(obase + gn + ty + j * 8) * C_SZ + gk + tx;
        h[o] = (char)hh;
        l[o] = (char)ll;
    }
}

// ---------------------------------------------------------------------------
// Transpose + bf16 split: Wo [K][N] fp32 -> hi/lo [N][K] bf16
// ---------------------------------------------------------------------------
__global__ void tsplit_kernel(const float* __restrict__ W, bf16* __restrict__ hi,
                              bf16* __restrict__ lo, int K, int N) {
    __shared__ float s[32][33];
    int tx = threadIdx.x, ty = threadIdx.y;     // 32 x 8
    int gn = blockIdx.x * 32, gk = blockIdx.y * 32;
#pragma unroll
    for (int j = 0; j < 4; j++)
        s[ty + j * 8][tx] = W[(size_t)(gk + ty + j * 8) * N + gn + tx];
    __syncthreads();
#pragma unroll
    for (int j = 0; j < 4; j++) {
        float v = s[tx][ty + j * 8];
        bf16 h = __float2bfloat16(v);
        size_t o = (size_t)(gn + ty + j * 8) * K + gk + tx;
        hi[o] = h;
        lo[o] = __float2bfloat16(v - __bfloat162float(h));
    }
}

// Elementwise fp32 -> bf16 hi/lo split (for y)
__global__ void split_kernel(const float* __restrict__ x, bf16* __restrict__ hi,
                             bf16* __restrict__ lo, int n) {
    int i = blockIdx.x * blockDim.x + threadIdx.x;
    if (i >= n) return;
    float v = x[i];
    bf16 h = __float2bfloat16(v);
    hi[i] = h;
    lo[i] = __float2bfloat16(v - __bfloat162float(h));
}

// ---------------------------------------------------------------------------
// int8 3-product limb GEMM (QKV): C = A @ Bt^T
// out = (accH*65536 + accX*256) * invSS  (ll term dropped: ~2e-7 relative)
// CTA 128x128, BK=64B, 512 threads, 2-stage cp.async, prefetch-before-wait.
// ---------------------------------------------------------------------------
#define IBM 128
#define IBN 128
#define IBK 64
#define ISTR 80
#define IPLANE (128 * ISTR)
#define ISTAGE (4 * IPLANE)         // 40960
#define IWRD 20
#define IR8 160

__global__ __launch_bounds__(512, 1) void gemm_i8(const char* __restrict__ Ah,
                                                  const char* __restrict__ Al,
                                                  const char* __restrict__ Bh,
                                                  const char* __restrict__ Bl,
                                                  float* __restrict__ C,
                                                  int M, int N, int K, float invSS) {
    extern __shared__ char sm8[];
    int tid = threadIdx.x, w = tid >> 5, lane = tid & 31;
    int g = lane >> 2, tg = lane & 3;
    int wm = (w & 3) * 32, wn = (w >> 2) * 32;
    int brow = blockIdx.y * IBM, bcol = blockIdx.x * IBN;

    int accH[2][4][4] = {};
    int accX[2][4][4] = {};

    const char* pb[4] = { Ah + (size_t)brow * K, Al + (size_t)brow * K,
                          Bh + (size_t)bcol * K, Bl + (size_t)bcol * K };

    auto fill = [&](int t, int s) {
        char* stg = sm8 + s * ISTAGE;
#pragma unroll
        for (int i = 0; i < 4; i++) {
            int idx = tid + i * 512;
            int plane = idx >> 9;        // == i
            int rem = idx & 511;
            int row = rem >> 2, ch = rem & 3;
            const char* src = pb[plane] + (size_t)row * K + t * IBK + ch * 16;
            unsigned d = smem_u32(stg + plane * IPLANE + row * ISTR + ch * 16);
            CP_ASYNC16(d, src);
        }
        asm volatile("cp.async.commit_group;\n");
    };

    const int nT = K / IBK;   // 32
    fill(0, 0);

    for (int t = 0; t < nT; t++) {
        if (t + 1 < nT) {
            fill(t + 1, (t + 1) & 1);
            asm volatile("cp.async.wait_group 1;\n");
        } else {
            asm volatile("cp.async.wait_group 0;\n");
        }
        __syncthreads();

        const int* base = (const int*)(sm8 + (t & 1) * ISTAGE);
        const int* ah = base;
        const int* al = base + IPLANE / 4;
        const int* bh = base + 2 * IPLANE / 4;
        const int* bl = base + 3 * IPLANE / 4;

#pragma unroll
        for (int ks = 0; ks < 2; ks++) {
            int kw = ks * 8 + tg;
            int Af[2][4], Lf[2][4];
#pragma unroll
            for (int mt = 0; mt < 2; mt++) {
                const int* p = ah + (wm + mt * 16 + g) * IWRD + kw;
                Af[mt][0] = p[0];  Af[mt][1] = p[IR8];
                Af[mt][2] = p[4];  Af[mt][3] = p[IR8 + 4];
                const int* q = al + (wm + mt * 16 + g) * IWRD + kw;
                Lf[mt][0] = q[0];  Lf[mt][1] = q[IR8];
                Lf[mt][2] = q[4];  Lf[mt][3] = q[IR8 + 4];
            }
#pragma unroll
            for (int nt = 0; nt < 4; nt++) {
                int Bf[2], Bg[2];
                const int* p = bh + (wn + nt * 8 + g) * IWRD + kw;
                Bf[0] = p[0];  Bf[1] = p[4];
                const int* q = bl + (wn + nt * 8 + g) * IWRD + kw;
                Bg[0] = q[0];  Bg[1] = q[4];
#pragma unroll
                for (int mt = 0; mt < 2; mt++) {
                    MMA_S8(accH[mt][nt], Af[mt], Bf);
                    MMA_S8(accX[mt][nt], Af[mt], Bg);
                    MMA_S8(accX[mt][nt], Lf[mt], Bf);
                }
            }
        }
        __syncthreads();
    }

#pragma unroll
    for (int mt = 0; mt < 2; mt++) {
        int r0 = brow + wm + mt * 16 + g;
#pragma unroll
        for (int nt = 0; nt < 4; nt++) {
            int c0 = bcol + wn + nt * 8 + tg * 2;
            float v0 = ((float)accH[mt][nt][0] * 65536.0f + (float)accX[mt][nt][0] * 256.0f) * invSS;
            float v1 = ((float)accH[mt][nt][1] * 65536.0f + (float)accX[mt][nt][1] * 256.0f) * invSS;
            float v2 = ((float)accH[mt][nt][2] * 65536.0f + (float)accX[mt][nt][2] * 256.0f) * invSS;
            float v3 = ((float)accH[mt][nt][3] * 65536.0f + (float)accX[mt][nt][3] * 256.0f) * invSS;
            *(float2*)&C[(size_t)r0 * N + c0] = make_float2(v0, v1);
            *(float2*)&C[(size_t)(r0 + 8) * N + c0] = make_float2(v2, v3);
        }
    }
}

// ---------------------------------------------------------------------------
// bf16x3 tensor-core GEMM (Wo projection) — R4 passing version
// ---------------------------------------------------------------------------
#define BBM 128
#define BBN 128
#define BBK 32
#define KSTR 40
#define BPLANE (128 * KSTR)
#define BPLANE32 (BPLANE / 2)

__global__ __launch_bounds__(256) void gemm_b3(const bf16* __restrict__ Ah,
                                               const bf16* __restrict__ Al,
                                               const bf16* __restrict__ Bh,
                                               const bf16* __restrict__ Bl,
                                               float* __restrict__ C,
                                               int M, int N, int K) {
    extern __shared__ bf16 smb[];

    int tid = threadIdx.x;
    int warp = tid >> 5, lane = tid & 31;
    int g = lane >> 2, tg = lane & 3;
    int wm = (warp & 1) * 64;
    int wn = (warp >> 1) * 32;
    int brow = blockIdx.y * BBM, bcol = blockIdx.x * BBN;

    float acc[4][4][4] = {};
    const int nK = K / BBK;

    auto loadTile = [&](int kt, int buf) {
        bf16* dstb = smb + buf * (4 * BPLANE);
#pragma unroll
        for (int i = 0; i < 8; i++) {
            int idx = tid + i * 256;
            int plane = idx >> 9;
            int rem = idx & 511;
            int row = rem >> 2, c = rem & 3;
            const bf16* src;
            if (plane == 0)      src = Ah + (size_t)(brow + row) * K;
            else if (plane == 1) src = Al + (size_t)(brow + row) * K;
            else if (plane == 2) src = Bh + (size_t)(bcol + row) * K;
            else                 src = Bl + (size_t)(bcol + row) * K;
            src += kt * BBK + c * 8;
            unsigned d = smem_u32(dstb + plane * BPLANE + row * KSTR + c * 8);
            CP_ASYNC16(d, src);
        }
        asm volatile("cp.async.commit_group;\n");
    };

    loadTile(0, 0);

    for (int kt = 0; kt < nK; kt++) {
        if (kt + 1 < nK) {
            loadTile(kt + 1, (kt + 1) & 1);
            asm volatile("cp.async.wait_group 1;\n");
        } else {
            asm volatile("cp.async.wait_group 0;\n");
        }
        __syncthreads();

        const unsigned* ah = (const unsigned*)(smb + (kt & 1) * (4 * BPLANE));
        const unsigned* al = ah + BPLANE32;
        const unsigned* bh = ah + 2 * BPLANE32;
        const unsigned* bl = ah + 3 * BPLANE32;

#pragma unroll
        for (int ks = 0; ks < 2; ks++) {
            int kc = ks * 8 + tg;
            unsigned Afh[4][4], Afl[4][4], Bfh[4][2], Bfl[4][2];
#pragma unroll
            for (int mt = 0; mt < 4; mt++) {
                int o = (wm + mt * 16 + g) * 20 + kc;
                Afh[mt][0] = ah[o];       Afh[mt][1] = ah[o + 160];
                Afh[mt][2] = ah[o + 4];   Afh[mt][3] = ah[o + 164];
                Afl[mt][0] = al[o];       Afl[mt][1] = al[o + 160];
                Afl[mt][2] = al[o + 4];   Afl[mt][3] = al[o + 164];
            }
#pragma unroll
            for (int nt = 0; nt < 4; nt++) {
                int o = (wn + nt * 8 + g) * 20 + kc;
                Bfh[nt][0] = bh[o];  Bfh[nt][1] = bh[o + 4];
                Bfl[nt][0] = bl[o];  Bfl[nt][1] = bl[o + 4];
            }
#pragma unroll
            for (int mt = 0; mt < 4; mt++)
#pragma unroll
                for (int nt = 0; nt < 4; nt++) {
                    MMA_BF16(acc[mt][nt], Afh[mt], Bfh[nt]);
                    MMA_BF16(acc[mt][nt], Afh[mt], Bfl[nt]);
                    MMA_BF16(acc[mt][nt], Afl[mt], Bfh[nt]);
                }
        }
        __syncthreads();
    }

#pragma unroll
    for (int mt = 0; mt < 4; mt++) {
        int r0 = brow + wm + mt * 16 + g;
#pragma unroll
        for (int nt = 0; nt < 4; nt++) {
            int c0 = bcol + wn + nt * 8 + tg * 2;
            *(float2*)&C[(size_t)r0 * N + c0] = make_float2(acc[mt][nt][0], acc[mt][nt][1]);
            *(float2*)&C[(size_t)(r0 + 8) * N + c0] = make_float2(acc[mt][nt][2], acc[mt][nt][3]);
        }
    }
}

// ---------------------------------------------------------------------------
// Fused RoPE + tf32-rna rounding over packed QKV.
// 48 slots: 0-31 q rope (fp32), 32-39 k rope+rna, 40-47 v rna only.
// ---------------------------------------------------------------------------
__global__ void rope_fused(float* __restrict__ qkv) {
    int idx = blockIdx.x * blockDim.x + threadIdx.x;
    int total = ROWS * 48 * 32;
    if (idx >= total) return;
    int i = idx & 31;
    int hh = (idx >> 5) % 48;
    int row = idx / (48 * 32);

    float* p;
    if (hh < 32)      p = qkv + (size_t)row * QKVLD + hh * HD;
    else if (hh < 40) p = qkv + (size_t)row * QKVLD + 2048 + (hh - 32) * HD;
    else              p = qkv + (size_t)row * QKVLD + 2560 + (hh - 40) * HD;

    if (hh >= 40) {   // v: round to tf32-rna only
        p[i]      = __uint_as_float(cvt_tf32(p[i]));
        p[i + 32] = __uint_as_float(cvt_tf32(p[i + 32]));
        return;
    }

    int t = row & (T_SZ - 1);
    float invf = expf(-(float)i * 0.28782313662425574f);  // ln(10000)/32
    float ang = (float)t * invf;
    float c = cosf(ang), s = sinf(ang);

    float x0 = p[i];
    float x1 = p[i + 32];
    float r0 = x0 * c - x1 * s;
    float r1 = x1 * c + x0 * s;
    if (hh >= 32) {   // k: rope + rna round
        p[i]      = __uint_as_float(cvt_tf32(r0));
        p[i + 32] = __uint_as_float(cvt_tf32(r1));
    } else {          // q: rope, fp32 (rna happens in flash)
        p[i]      = r0;
        p[i + 32] = r1;
    }
}

// ---------------------------------------------------------------------------
// TF32 tensor-core flash attention (causal) — fused-QKV layout (stride 3072)
// ---------------------------------------------------------------------------
#define FQ 128
#define FK 64
#define FSTR 68
#define FBUF (FK * FSTR * 2)

__global__ __launch_bounds__(256, 2) void flash_tc(const float* __restrict__ qkv,
                                                   float* __restrict__ y) {
    extern __shared__ float smf[];
    int qt = blockIdx.x, h = blockIdx.y, b = blockIdx.z;
    int hk = h >> 2;
    int tid = threadIdx.x, w = tid >> 5, lane = tid & 31;
    int g = lane >> 2, tg = lane & 3;
    int qbase = qt * FQ;
    size_t bT = (size_t)b * T_SZ;

    {
        const float* qg = qkv + (bT + qbase) * QKVLD + h * HD;
#pragma unroll
        for (int i = 0; i < 8; i++) {
            int idx = tid + i * 256;
            int r = idx >> 4, c4 = (idx & 15) * 4;
            unsigned d = smem_u32(smf + r * FSTR + c4);
            CP_ASYNC16(d, qg + (size_t)r * QKVLD + c4);
        }
        asm volatile("cp.async.commit_group;\ncp.async.wait_group 0;\n");
    }
    __syncthreads();

    unsigned qa[8][4];
    {
        int r0 = w * 16 + g;
#pragma unroll
        for (int c = 0; c < 8; c++) {
            qa[c][0] = cvt_tf32(smf[r0 * FSTR + 8 * c + tg] * 0.125f);
            qa[c][1] = cvt_tf32(smf[(r0 + 8) * FSTR + 8 * c + tg] * 0.125f);
            qa[c][2] = cvt_tf32(smf[r0 * FSTR + 8 * c + tg + 4] * 0.125f);
            qa[c][3] = cvt_tf32(smf[(r0 + 8) * FSTR + 8 * c + tg + 4] * 0.125f);
        }
    }
    __syncthreads();

    auto loadKV = [&](int kt, int buf) {
        float* base = smf + buf * FBUF;
        const float* kg = qkv + (bT + kt * FK) * QKVLD + 2048 + hk * HD;
        const float* vg = qkv + (bT + kt * FK) * QKVLD + 2560 + hk * HD;
#pragma unroll
        for (int i = 0; i < 4; i++) {
            int idx = tid + i * 256;
            int r = idx >> 4, c4 = (idx & 15) * 4;
            unsigned dk = smem_u32(base + r * FSTR + c4);
            CP_ASYNC16(dk, kg + (size_t)r * QKVLD + c4);
            unsigned dv = smem_u32(base + FK * FSTR + r * FSTR + c4);
            CP_ASYNC16(dv, vg + (size_t)r * QKVLD + c4);
        }
        asm volatile("cp.async.commit_group;\n");
    };

    float yacc[8][4] = {};
    float m0 = -INFINITY, m1 = -INFINITY, l0 = 0.0f, l1 = 0.0f;
    int rg0 = qbase + w * 16 + g;

    int nkt = 2 * qt + 2;
    loadKV(0, 0);

    for (int kt = 0; kt < nkt; kt++) {
        if (kt + 1 < nkt) {
            loadKV(kt + 1, (kt + 1) & 1);
            asm volatile("cp.async.wait_group 1;\n");
        } else {
            asm volatile("cp.async.wait_group 0;\n");
        }
        __syncthreads();

        bool active = (FK * kt <= qbase + 16 * w + 15);
        if (active) {
            const float* Ks = smf + (kt & 1) * FBUF;
            const float* Vs = Ks + FK * FSTR;

            float sacc[8][4] = {};
#pragma unroll
            for (int c = 0; c < 8; c++) {
#pragma unroll
                for (int nf = 0; nf < 8; nf++) {
                    unsigned bb[2];
                    bb[0] = __float_as_uint(Ks[(8 * nf + g) * FSTR + 8 * c + tg]);
                    bb[1] = __float_as_uint(Ks[(8 * nf + g) * FSTR + 8 * c + tg + 4]);
                    MMA_TF32(sacc[nf], qa[c], bb);
                }
            }

            if (kt >= 2 * qt) {
                int k0 = FK * kt;
#pragma unroll
                for (int nf = 0; nf < 8; nf++) {
                    int jg = k0 + 8 * nf + 2 * tg;
                    if (jg > rg0)     sacc[nf][0] = -INFINITY;
                    if (jg + 1 > rg0) sacc[nf][1] = -INFINITY;
                    if (jg > rg0 + 8)     sacc[nf][2] = -INFINITY;
                    if (jg + 1 > rg0 + 8) sacc[nf][3] = -INFINITY;
                }
            }

            float mt0 = -INFINITY, mt1 = -INFINITY;
#pragma unroll
            for (int nf = 0; nf < 8; nf++) {
                mt0 = fmaxf(mt0, fmaxf(sacc[nf][0], sacc[nf][1]));
                mt1 = fmaxf(mt1, fmaxf(sacc[nf][2], sacc[nf][3]));
            }
            mt0 = fmaxf(mt0, __shfl_xor_sync(0xffffffffu, mt0, 1));
            mt0 = fmaxf(mt0, __shfl_xor_sync(0xffffffffu, mt0, 2));
            mt1 = fmaxf(mt1, __shfl_xor_sync(0xffffffffu, mt1, 1));
            mt1 = fmaxf(mt1, __shfl_xor_sync(0xffffffffu, mt1, 2));

            float mn0 = fmaxf(m0, mt0), mn1 = fmaxf(m1, mt1);
            float al0 = __expf(m0 - mn0), al1 = __expf(m1 - mn1);
            m0 = mn0; m1 = mn1;
#pragma unroll
            for (int nf = 0; nf < 8; nf++) {
                yacc[nf][0] *= al0; yacc[nf][1] *= al0;
                yacc[nf][2] *= al1; yacc[nf][3] *= al1;
            }

            float pl0 = 0.0f, pl1 = 0.0f;
#pragma unroll
            for (int c = 0; c < 8; c++) {
                float p0 = __expf(sacc[c][0] - mn0);
                float p1 = __expf(sacc[c][1] - mn0);
                float p2 = __expf(sacc[c][2] - mn1);
                float p3 = __expf(sacc[c][3] - mn1);
                pl0 += p0 + p1;
                pl1 += p2 + p3;
                unsigned pa[4];
                pa[0] = cvt_tf32(p0);
                pa[1] = cvt_tf32(p2);
                pa[2] = cvt_tf32(p1);
                pa[3] = cvt_tf32(p3);
#pragma unroll
                for (int nf = 0; nf < 8; nf++) {
                    unsigned bb[2];
                    bb[0] = __float_as_uint(Vs[(8 * c + 2 * tg) * FSTR + 8 * nf + g]);
                    bb[1] = __float_as_uint(Vs[(8 * c + 2 * tg + 1) * FSTR + 8 * nf + g]);
                    MMA_TF32(yacc[nf], pa, bb);
                }
            }
            pl0 += __shfl_xor_sync(0xffffffffu, pl0, 1);
            pl0 += __shfl_xor_sync(0xffffffffu, pl0, 2);
            pl1 += __shfl_xor_sync(0xffffffffu, pl1, 1);
            pl1 += __shfl_xor_sync(0xffffffffu, pl1, 2);
            l0 = l0 * al0 + pl0;
            l1 = l1 * al1 + pl1;
        }
        __syncthreads();
    }

    float inv0 = 1.0f / l0, inv1 = 1.0f / l1;
    float* yo0 = y + (bT + qbase + w * 16 + g) * C_SZ + h * HD;
    float* yo1 = yo0 + 8 * C_SZ;
#pragma unroll
    for (int nf = 0; nf < 8; nf++) {
        *(float2*)&yo0[8 * nf + 2 * tg] = make_float2(yacc[nf][0] * inv0, yacc[nf][1] * inv0);
        *(float2*)&yo1[8 * nf + 2 * tg] = make_float2(yacc[nf][2] * inv1, yacc[nf][3] * inv1);
    }
}

// ---------------------------------------------------------------------------
extern "C" void kernel_launch(void* const* d_in, const int* in_sizes, int n_in,
                              void* d_out, int out_size) {
    const float* x  = (const float*)d_in[0];
    const float* Wq = (const float*)d_in[1];
    const float* Wk = (const float*)d_in[2];
    const float* Wv = (const float*)d_in[3];
    const float* Wo = (const float*)d_in[4];
    float* out = (float*)d_out;

    float *pqkv, *py;
    cudaGetSymbolAddress((void**)&pqkv, g_qkv);
    cudaGetSymbolAddress((void**)&py, g_y);

    char *xh, *xl, *wh, *wl;
    cudaGetSymbolAddress((void**)&xh, g_xh8); cudaGetSymbolAddress((void**)&xl, g_xl8);
    cudaGetSymbolAddress((void**)&wh, g_wh8); cudaGetSymbolAddress((void**)&wl, g_wl8);
    bf16 *yh, *yl, *woh, *wol;
    cudaGetSymbolAddress((void**)&yh, g_yh);  cudaGetSymbolAddress((void**)&yl, g_yl);
    cudaGetSymbolAddress((void**)&woh, g_woh); cudaGetSymbolAddress((void**)&wol, g_wol);

    int ismem = 2 * ISTAGE;                        // 81920
    cudaFuncSetAttribute(gemm_i8, cudaFuncAttributeMaxDynamicSharedMemorySize, ismem);
    int bsmem = 2 * 4 * BPLANE * (int)sizeof(bf16);// 81920
    cudaFuncSetAttribute(gemm_b3, cudaFuncAttributeMaxDynamicSharedMemorySize, bsmem);
    int fsmem = 2 * FBUF * (int)sizeof(float);     // 69632
    cudaFuncSetAttribute(flash_tc, cudaFuncAttributeMaxDynamicSharedMemorySize, fsmem);

    const float invSS = (float)(1.0 / ((double)S_ACT * (double)S_WGT));

    // (0) quantize x; (1) QKV weight limbs; (2) Wo bf16 planes
    {
        int n = ROWS * C_SZ;
        q8_kernel<<<(n + 255) / 256, 256>>>(x, xh, xl, n, S_ACT);
    }
    tq8_qkv<<<dim3(96, C_SZ / 32), dim3(32, 8)>>>(Wq, Wk, Wv, wh, wl);
    tsplit_kernel<<<dim3(C_SZ / 32, C_SZ / 32), dim3(32, 8)>>>(Wo, woh, wol, C_SZ, C_SZ);

    // (3) fused QKV projection (int8 limb IMMA, prefetch-pipelined)
    gemm_i8<<<dim3(QKVLD / IBN, ROWS / IBM), 512, ismem>>>(
        xh, xl, wh, wl, pqkv, ROWS, QKVLD, C_SZ, invSS);

    // (4) fused RoPE + k/v tf32-rna rounding
    {
        int tot = ROWS * 48 * 32;
        rope_fused<<<(tot + 255) / 256, 256>>>(pqkv);
    }

    // (5) flash attention (tf32)  <- ncu capture slot (-s 5)
    flash_tc<<<dim3(T_SZ / FQ, NH, B_SZ), 256, fsmem>>>(pqkv, py);

    // (6) split y, (7) output projection (bf16x3)
    {
        int n = ROWS * C_SZ;
        split_kernel<<<(n + 255) / 256, 256>>>(py, yh, yl, n);
        gemm_b3<<<dim3(C_SZ / BBN, ROWS / BBM), 256, bsmem>>>(
            yh, yl, woh, wol, out, ROWS, C_SZ, C_SZ);
    }
}

// round 12
// speedup vs baseline: 1.8600x; 1.6158x over previous
#include <cuda_runtime.h>
#include <cuda_bf16.h>
#include <math.h>
#include <stdint.h>

// Problem constants
#define B_SZ 2
#define T_SZ 2048
#define C_SZ 2048
#define NH 32
#define NKV 8
#define HD 64
#define ROWS (B_SZ * T_SZ)          // 4096
#define QKVLD 3072                  // fused qkv row stride

typedef __nv_bfloat16 bf16;

// Scratch (allocation-free: __device__ globals)
__device__ float g_qkv[ROWS * QKVLD];

__device__ bf16 g_xh[ROWS * C_SZ], g_xl[ROWS * C_SZ];
__device__ bf16 g_yh[ROWS * C_SZ], g_yl[ROWS * C_SZ];
__device__ bf16 g_wh[QKVLD * C_SZ], g_wl[QKVLD * C_SZ];    // [Wq|Wk|Wv]^T planes
__device__ bf16 g_woh[C_SZ * C_SZ], g_wol[C_SZ * C_SZ];    // Wo^T planes

// ---------------------------------------------------------------------------
#define CP_ASYNC16(dst, src) \
    asm volatile("cp.async.cg.shared.global [%0], [%1], 16;\n" :: "r"(dst), "l"(src))

__device__ __forceinline__ unsigned cvt_tf32(float f) {
    unsigned u;
    asm("cvt.rna.tf32.f32 %0, %1;" : "=r"(u) : "f"(f));
    return u;
}

__device__ __forceinline__ uint32_t smem_u32(const void* p) {
    uint32_t a;
    asm("{ .reg .u64 t; cvta.to.shared.u64 t, %1; cvt.u32.u64 %0, t; }" : "=r"(a) : "l"(p));
    return a;
}

#define MMA_TF32(d, a, b) \
    asm volatile("mma.sync.aligned.m16n8k8.row.col.f32.tf32.tf32.f32 " \
                 "{%0,%1,%2,%3}, {%4,%5,%6,%7}, {%8,%9}, {%0,%1,%2,%3};\n" \
                 : "+f"(d[0]), "+f"(d[1]), "+f"(d[2]), "+f"(d[3]) \
                 : "r"(a[0]), "r"(a[1]), "r"(a[2]), "r"(a[3]), "r"(b[0]), "r"(b[1]))

#define MMA_BF16(d, a, b) \
    asm volatile("mma.sync.aligned.m16n8k16.row.col.f32.bf16.bf16.f32 " \
                 "{%0,%1,%2,%3}, {%4,%5,%6,%7}, {%8,%9}, {%0,%1,%2,%3};\n" \
                 : "+f"(d[0]), "+f"(d[1]), "+f"(d[2]), "+f"(d[3]) \
                 : "r"(a[0]), "r"(a[1]), "r"(a[2]), "r"(a[3]), "r"(b[0]), "r"(b[1]))

// ---------------------------------------------------------------------------
// Elementwise fp32 -> bf16 hi/lo split (for x)
// ---------------------------------------------------------------------------
__global__ void split_kernel(const float* __restrict__ x, bf16* __restrict__ hi,
                             bf16* __restrict__ lo, int n) {
    int i = blockIdx.x * blockDim.x + threadIdx.x;
    if (i >= n) return;
    float v = x[i];
    bf16 h = __float2bfloat16(v);
    hi[i] = h;
    lo[i] = __float2bfloat16(v - __bfloat162float(h));
}

// ---------------------------------------------------------------------------
// Transpose + split fused QKV weights: Wq/Wk/Wv [K][N] -> planes [3072][2048]
// grid.x: 0-63 Wq, 64-79 Wk, 80-95 Wv; grid.y: K/32
// ---------------------------------------------------------------------------
__global__ void tsplit_qkv(const float* __restrict__ Wq, const float* __restrict__ Wk,
                           const float* __restrict__ Wv, bf16* __restrict__ hi,
                           bf16* __restrict__ lo) {
    __shared__ float s[32][33];
    int tx = threadIdx.x, ty = threadIdx.y;     // 32 x 8
    int bx = blockIdx.x, gk = blockIdx.y * 32;
    const float* W;
    int N, nb, obase;
    if (bx < 64)      { W = Wq; N = 2048; nb = bx;      obase = 0; }
    else if (bx < 80) { W = Wk; N = 512;  nb = bx - 64; obase = 2048; }
    else              { W = Wv; N = 512;  nb = bx - 80; obase = 2560; }
    int gn = nb * 32;
#pragma unroll
    for (int j = 0; j < 4; j++)
        s[ty + j * 8][tx] = W[(size_t)(gk + ty + j * 8) * N + gn + tx];
    __syncthreads();
#pragma unroll
    for (int j = 0; j < 4; j++) {
        float v = s[tx][ty + j * 8];
        bf16 h = __float2bfloat16(v);
        size_t o = (size_t)(obase + gn + ty + j * 8) * C_SZ + gk + tx;
        hi[o] = h;
        lo[o] = __float2bfloat16(v - __bfloat162float(h));
    }
}

// Transpose + split single weight Wo [K][N] -> [N][K]
__global__ void tsplit_kernel(const float* __restrict__ W, bf16* __restrict__ hi,
                              bf16* __restrict__ lo, int K, int N) {
    __shared__ float s[32][33];
    int tx = threadIdx.x, ty = threadIdx.y;     // 32 x 8
    int gn = blockIdx.x * 32, gk = blockIdx.y * 32;
#pragma unroll
    for (int j = 0; j < 4; j++)
        s[ty + j * 8][tx] = W[(size_t)(gk + ty + j * 8) * N + gn + tx];
    __syncthreads();
#pragma unroll
    for (int j = 0; j < 4; j++) {
        float v = s[tx][ty + j * 8];
        bf16 h = __float2bfloat16(v);
        size_t o = (size_t)(gn + ty + j * 8) * K + gk + tx;
        hi[o] = h;
        lo[o] = __float2bfloat16(v - __bfloat162float(h));
    }
}

// ---------------------------------------------------------------------------
// bf16x3 tensor-core GEMM (R4-proven): C[M,N] = A[M,K] @ Bt[N,K]^T
// Block 128x128x32, 256 threads, warp 64x32, m16n8k16 bf16, 2-stage cp.async.
// ---------------------------------------------------------------------------
#define BBM 128
#define BBN 128
#define BBK 32
#define KSTR 40
#define BPLANE (128 * KSTR)
#define BPLANE32 (BPLANE / 2)

__global__ __launch_bounds__(256) void gemm_b3(const bf16* __restrict__ Ah,
                                               const bf16* __restrict__ Al,
                                               const bf16* __restrict__ Bh,
                                               const bf16* __restrict__ Bl,
                                               float* __restrict__ C,
                                               int M, int N, int K) {
    extern __shared__ bf16 smb[];

    int tid = threadIdx.x;
    int warp = tid >> 5, lane = tid & 31;
    int g = lane >> 2, tg = lane & 3;
    int wm = (warp & 1) * 64;
    int wn = (warp >> 1) * 32;
    int brow = blockIdx.y * BBM, bcol = blockIdx.x * BBN;

    float acc[4][4][4] = {};
    const int nK = K / BBK;

    auto loadTile = [&](int kt, int buf) {
        bf16* dstb = smb + buf * (4 * BPLANE);
#pragma unroll
        for (int i = 0; i < 8; i++) {
            int idx = tid + i * 256;
            int plane = idx >> 9;
            int rem = idx & 511;
            int row = rem >> 2, c = rem & 3;
            const bf16* src;
            if (plane == 0)      src = Ah + (size_t)(brow + row) * K;
            else if (plane == 1) src = Al + (size_t)(brow + row) * K;
            else if (plane == 2) src = Bh + (size_t)(bcol + row) * K;
            else                 src = Bl + (size_t)(bcol + row) * K;
            src += kt * BBK + c * 8;
            unsigned d = smem_u32(dstb + plane * BPLANE + row * KSTR + c * 8);
            CP_ASYNC16(d, src);
        }
        asm volatile("cp.async.commit_group;\n");
    };

    loadTile(0, 0);

    for (int kt = 0; kt < nK; kt++) {
        if (kt + 1 < nK) {
            loadTile(kt + 1, (kt + 1) & 1);
            asm volatile("cp.async.wait_group 1;\n");
        } else {
            asm volatile("cp.async.wait_group 0;\n");
        }
        __syncthreads();

        const unsigned* ah = (const unsigned*)(smb + (kt & 1) * (4 * BPLANE));
        const unsigned* al = ah + BPLANE32;
        const unsigned* bh = ah + 2 * BPLANE32;
        const unsigned* bl = ah + 3 * BPLANE32;

#pragma unroll
        for (int ks = 0; ks < 2; ks++) {
            int kc = ks * 8 + tg;
            unsigned Afh[4][4], Afl[4][4], Bfh[4][2], Bfl[4][2];
#pragma unroll
            for (int mt = 0; mt < 4; mt++) {
                int o = (wm + mt * 16 + g) * 20 + kc;
                Afh[mt][0] = ah[o];       Afh[mt][1] = ah[o + 160];
                Afh[mt][2] = ah[o + 4];   Afh[mt][3] = ah[o + 164];
                Afl[mt][0] = al[o];       Afl[mt][1] = al[o + 160];
                Afl[mt][2] = al[o + 4];   Afl[mt][3] = al[o + 164];
            }
#pragma unroll
            for (int nt = 0; nt < 4; nt++) {
                int o = (wn + nt * 8 + g) * 20 + kc;
                Bfh[nt][0] = bh[o];  Bfh[nt][1] = bh[o + 4];
                Bfl[nt][0] = bl[o];  Bfl[nt][1] = bl[o + 4];
            }
#pragma unroll
            for (int mt = 0; mt < 4; mt++)
#pragma unroll
                for (int nt = 0; nt < 4; nt++) {
                    MMA_BF16(acc[mt][nt], Afh[mt], Bfh[nt]);
                    MMA_BF16(acc[mt][nt], Afh[mt], Bfl[nt]);
                    MMA_BF16(acc[mt][nt], Afl[mt], Bfh[nt]);
                }
        }
        __syncthreads();
    }

#pragma unroll
    for (int mt = 0; mt < 4; mt++) {
        int r0 = brow + wm + mt * 16 + g;
#pragma unroll
        for (int nt = 0; nt < 4; nt++) {
            int c0 = bcol + wn + nt * 8 + tg * 2;
            *(float2*)&C[(size_t)r0 * N + c0] = make_float2(acc[mt][nt][0], acc[mt][nt][1]);
            *(float2*)&C[(size_t)(r0 + 8) * N + c0] = make_float2(acc[mt][nt][2], acc[mt][nt][3]);
        }
    }
}

// ---------------------------------------------------------------------------
// Fused RoPE + tf32-rna rounding over packed QKV.
// 48 slots: 0-31 q rope (fp32), 32-39 k rope+rna, 40-47 v rna only.
// ---------------------------------------------------------------------------
__global__ void rope_fused(float* __restrict__ qkv) {
    int idx = blockIdx.x * blockDim.x + threadIdx.x;
    int total = ROWS * 48 * 32;
    if (idx >= total) return;
    int i = idx & 31;
    int hh = (idx >> 5) % 48;
    int row = idx / (48 * 32);

    float* p;
    if (hh < 32)      p = qkv + (size_t)row * QKVLD + hh * HD;
    else if (hh < 40) p = qkv + (size_t)row * QKVLD + 2048 + (hh - 32) * HD;
    else              p = qkv + (size_t)row * QKVLD + 2560 + (hh - 40) * HD;

    if (hh >= 40) {   // v: tf32-rna round only
        p[i]      = __uint_as_float(cvt_tf32(p[i]));
        p[i + 32] = __uint_as_float(cvt_tf32(p[i + 32]));
        return;
    }

    int t = row & (T_SZ - 1);
    float invf = expf(-(float)i * 0.28782313662425574f);  // ln(10000)/32
    float ang = (float)t * invf;
    float c = cosf(ang), s = sinf(ang);

    float x0 = p[i];
    float x1 = p[i + 32];
    float r0 = x0 * c - x1 * s;
    float r1 = x1 * c + x0 * s;
    if (hh >= 32) {   // k: rope + rna round
        p[i]      = __uint_as_float(cvt_tf32(r0));
        p[i + 32] = __uint_as_float(cvt_tf32(r1));
    } else {          // q: rope, fp32
        p[i]      = r0;
        p[i + 32] = r1;
    }
}

// ---------------------------------------------------------------------------
// TF32 tensor-core flash attention (causal), fused-QKV input (stride 3072).
// Epilogue writes y directly as bf16 hi/lo planes (feeds Wo bf16x3 GEMM).
// ---------------------------------------------------------------------------
#define FQ 128
#define FK 64
#define FSTR 68
#define FBUF (FK * FSTR * 2)

__global__ __launch_bounds__(256, 2) void flash_tc(const float* __restrict__ qkv,
                                                   bf16* __restrict__ yh,
                                                   bf16* __restrict__ yl) {
    extern __shared__ float smf[];
    int qt = blockIdx.x, h = blockIdx.y, b = blockIdx.z;
    int hk = h >> 2;
    int tid = threadIdx.x, w = tid >> 5, lane = tid & 31;
    int g = lane >> 2, tg = lane & 3;
    int qbase = qt * FQ;
    size_t bT = (size_t)b * T_SZ;

    {
        const float* qg = qkv + (bT + qbase) * QKVLD + h * HD;
#pragma unroll
        for (int i = 0; i < 8; i++) {
            int idx = tid + i * 256;
            int r = idx >> 4, c4 = (idx & 15) * 4;
            unsigned d = smem_u32(smf + r * FSTR + c4);
            CP_ASYNC16(d, qg + (size_t)r * QKVLD + c4);
        }
        asm volatile("cp.async.commit_group;\ncp.async.wait_group 0;\n");
    }
    __syncthreads();

    unsigned qa[8][4];
    {
        int r0 = w * 16 + g;
#pragma unroll
        for (int c = 0; c < 8; c++) {
            qa[c][0] = cvt_tf32(smf[r0 * FSTR + 8 * c + tg] * 0.125f);
            qa[c][1] = cvt_tf32(smf[(r0 + 8) * FSTR + 8 * c + tg] * 0.125f);
            qa[c][2] = cvt_tf32(smf[r0 * FSTR + 8 * c + tg + 4] * 0.125f);
            qa[c][3] = cvt_tf32(smf[(r0 + 8) * FSTR + 8 * c + tg + 4] * 0.125f);
        }
    }
    __syncthreads();

    auto loadKV = [&](int kt, int buf) {
        float* base = smf + buf * FBUF;
        const float* kg = qkv + (bT + kt * FK) * QKVLD + 2048 + hk * HD;
        const float* vg = qkv + (bT + kt * FK) * QKVLD + 2560 + hk * HD;
#pragma unroll
        for (int i = 0; i < 4; i++) {
            int idx = tid + i * 256;
            int r = idx >> 4, c4 = (idx & 15) * 4;
            unsigned dk = smem_u32(base + r * FSTR + c4);
            CP_ASYNC16(dk, kg + (size_t)r * QKVLD + c4);
            unsigned dv = smem_u32(base + FK * FSTR + r * FSTR + c4);
            CP_ASYNC16(dv, vg + (size_t)r * QKVLD + c4);
        }
        asm volatile("cp.async.commit_group;\n");
    };

    float yacc[8][4] = {};
    float m0 = -INFINITY, m1 = -INFINITY, l0 = 0.0f, l1 = 0.0f;
    int rg0 = qbase + w * 16 + g;

    int nkt = 2 * qt + 2;
    loadKV(0, 0);

    for (int kt = 0; kt < nkt; kt++) {
        if (kt + 1 < nkt) {
            loadKV(kt + 1, (kt + 1) & 1);
            asm volatile("cp.async.wait_group 1;\n");
        } else {
            asm volatile("cp.async.wait_group 0;\n");
        }
        __syncthreads();

        bool active = (FK * kt <= qbase + 16 * w + 15);
        if (active) {
            const float* Ks = smf + (kt & 1) * FBUF;
            const float* Vs = Ks + FK * FSTR;

            float sacc[8][4] = {};
#pragma unroll
            for (int c = 0; c < 8; c++) {
#pragma unroll
                for (int nf = 0; nf < 8; nf++) {
                    unsigned bb[2];
                    bb[0] = __float_as_uint(Ks[(8 * nf + g) * FSTR + 8 * c + tg]);
                    bb[1] = __float_as_uint(Ks[(8 * nf + g) * FSTR + 8 * c + tg + 4]);
                    MMA_TF32(sacc[nf], qa[c], bb);
                }
            }

            if (kt >= 2 * qt) {
                int k0 = FK * kt;
#pragma unroll
                for (int nf = 0; nf < 8; nf++) {
                    int jg = k0 + 8 * nf + 2 * tg;
                    if (jg > rg0)     sacc[nf][0] = -INFINITY;
                    if (jg + 1 > rg0) sacc[nf][1] = -INFINITY;
                    if (jg > rg0 + 8)     sacc[nf][2] = -INFINITY;
                    if (jg + 1 > rg0 + 8) sacc[nf][3] = -INFINITY;
                }
            }

            float mt0 = -INFINITY, mt1 = -INFINITY;
#pragma unroll
            for (int nf = 0; nf < 8; nf++) {
                mt0 = fmaxf(mt0, fmaxf(sacc[nf][0], sacc[nf][1]));
                mt1 = fmaxf(mt1, fmaxf(sacc[nf][2], sacc[nf][3]));
            }
            mt0 = fmaxf(mt0, __shfl_xor_sync(0xffffffffu, mt0, 1));
            mt0 = fmaxf(mt0, __shfl_xor_sync(0xffffffffu, mt0, 2));
            mt1 = fmaxf(mt1, __shfl_xor_sync(0xffffffffu, mt1, 1));
            mt1 = fmaxf(mt1, __shfl_xor_sync(0xffffffffu, mt1, 2));

            float mn0 = fmaxf(m0, mt0), mn1 = fmaxf(m1, mt1);
            float al0 = __expf(m0 - mn0), al1 = __expf(m1 - mn1);
            m0 = mn0; m1 = mn1;
#pragma unroll
            for (int nf = 0; nf < 8; nf++) {
                yacc[nf][0] *= al0; yacc[nf][1] *= al0;
                yacc[nf][2] *= al1; yacc[nf][3] *= al1;
            }

            float pl0 = 0.0f, pl1 = 0.0f;
#pragma unroll
            for (int c = 0; c < 8; c++) {
                float p0 = __expf(sacc[c][0] - mn0);
                float p1 = __expf(sacc[c][1] - mn0);
                float p2 = __expf(sacc[c][2] - mn1);
                float p3 = __expf(sacc[c][3] - mn1);
                pl0 += p0 + p1;
                pl1 += p2 + p3;
                unsigned pa[4];
                pa[0] = cvt_tf32(p0);
                pa[1] = cvt_tf32(p2);
                pa[2] = cvt_tf32(p1);
                pa[3] = cvt_tf32(p3);
#pragma unroll
                for (int nf = 0; nf < 8; nf++) {
                    unsigned bb[2];
                    bb[0] = __float_as_uint(Vs[(8 * c + 2 * tg) * FSTR + 8 * nf + g]);
                    bb[1] = __float_as_uint(Vs[(8 * c + 2 * tg + 1) * FSTR + 8 * nf + g]);
                    MMA_TF32(yacc[nf], pa, bb);
                }
            }
            pl0 += __shfl_xor_sync(0xffffffffu, pl0, 1);
            pl0 += __shfl_xor_sync(0xffffffffu, pl0, 2);
            pl1 += __shfl_xor_sync(0xffffffffu, pl1, 1);
            pl1 += __shfl_xor_sync(0xffffffffu, pl1, 2);
            l0 = l0 * al0 + pl0;
            l1 = l1 * al1 + pl1;
        }
        __syncthreads();
    }

    // normalize + split to bf16 hi/lo planes (skips separate split kernel)
    float inv0 = 1.0f / l0, inv1 = 1.0f / l1;
    size_t r0 = (bT + qbase + w * 16 + g) * C_SZ + h * HD;
    size_t r1 = r0 + 8 * (size_t)C_SZ;
#pragma unroll
    for (int nf = 0; nf < 8; nf++) {
        int c0 = 8 * nf + 2 * tg;
        float v0 = yacc[nf][0] * inv0, v1 = yacc[nf][1] * inv0;
        float v2 = yacc[nf][2] * inv1, v3 = yacc[nf][3] * inv1;
        bf16 h0 = __float2bfloat16(v0), h1 = __float2bfloat16(v1);
        bf16 h2 = __float2bfloat16(v2), h3 = __float2bfloat16(v3);
        __nv_bfloat162 hp0; hp0.x = h0; hp0.y = h1;
        __nv_bfloat162 hp1; hp1.x = h2; hp1.y = h3;
        *(__nv_bfloat162*)&yh[r0 + c0] = hp0;
        *(__nv_bfloat162*)&yh[r1 + c0] = hp1;
        __nv_bfloat162 lp0, lp1;
        lp0.x = __float2bfloat16(v0 - __bfloat162float(h0));
        lp0.y = __float2bfloat16(v1 - __bfloat162float(h1));
        lp1.x = __float2bfloat16(v2 - __bfloat162float(h2));
        lp1.y = __float2bfloat16(v3 - __bfloat162float(h3));
        *(__nv_bfloat162*)&yl[r0 + c0] = lp0;
        *(__nv_bfloat162*)&yl[r1 + c0] = lp1;
    }
}

// ---------------------------------------------------------------------------
extern "C" void kernel_launch(void* const* d_in, const int* in_sizes, int n_in,
                              void* d_out, int out_size) {
    const float* x  = (const float*)d_in[0];
    const float* Wq = (const float*)d_in[1];
    const float* Wk = (const float*)d_in[2];
    const float* Wv = (const float*)d_in[3];
    const float* Wo = (const float*)d_in[4];
    float* out = (float*)d_out;

    float* pqkv;
    cudaGetSymbolAddress((void**)&pqkv, g_qkv);

    bf16 *xh, *xl, *yh, *yl, *wh, *wl, *woh, *wol;
    cudaGetSymbolAddress((void**)&xh, g_xh);  cudaGetSymbolAddress((void**)&xl, g_xl);
    cudaGetSymbolAddress((void**)&yh, g_yh);  cudaGetSymbolAddress((void**)&yl, g_yl);
    cudaGetSymbolAddress((void**)&wh, g_wh);  cudaGetSymbolAddress((void**)&wl, g_wl);
    cudaGetSymbolAddress((void**)&woh, g_woh); cudaGetSymbolAddress((void**)&wol, g_wol);

    int bsmem = 2 * 4 * BPLANE * (int)sizeof(bf16);   // 81920
    cudaFuncSetAttribute(gemm_b3, cudaFuncAttributeMaxDynamicSharedMemorySize, bsmem);
    int fsmem = 2 * FBUF * (int)sizeof(float);        // 69632
    cudaFuncSetAttribute(flash_tc, cudaFuncAttributeMaxDynamicSharedMemorySize, fsmem);

    // (0) split x; (1) fused QKV weight planes; (2) Wo planes
    {
        int n = ROWS * C_SZ;
        split_kernel<<<(n + 255) / 256, 256>>>(x, xh, xl, n);
    }
    tsplit_qkv<<<dim3(96, C_SZ / 32), dim3(32, 8)>>>(Wq, Wk, Wv, wh, wl);
    tsplit_kernel<<<dim3(C_SZ / 32, C_SZ / 32), dim3(32, 8)>>>(Wo, woh, wol, C_SZ, C_SZ);

    // (3) fused QKV projection (bf16x3, one launch)
    gemm_b3<<<dim3(QKVLD / BBN, ROWS / BBM), 256, bsmem>>>(
        xh, xl, wh, wl, pqkv, ROWS, QKVLD, C_SZ);

    // (4) fused RoPE + k/v tf32-rna rounding
    {
        int tot = ROWS * 48 * 32;
        rope_fused<<<(tot + 255) / 256, 256>>>(pqkv);
    }

    // (5) flash attention (tf32) -> y bf16 hi/lo planes   <- ncu slot (-s 5)
    flash_tc<<<dim3(T_SZ / FQ, NH, B_SZ), 256, fsmem>>>(pqkv, yh, yl);

    // (6) output projection (bf16x3)
    gemm_b3<<<dim3(C_SZ / BBN, ROWS / BBM), 256, bsmem>>>(
        yh, yl, woh, wol, out, ROWS, C_SZ, C_SZ);
}

// round 13
// speedup vs baseline: 2.0806x; 1.1186x over previous
#include <cuda_runtime.h>
#include <cuda_bf16.h>
#include <math.h>
#include <stdint.h>

// Problem constants
#define B_SZ 2
#define T_SZ 2048
#define C_SZ 2048
#define NH 32
#define NKV 8
#define HD 64
#define ROWS (B_SZ * T_SZ)          // 4096
#define QKVLD 3072                  // fused qkv row stride

typedef __nv_bfloat16 bf16;

// Scratch (allocation-free: __device__ globals)
__device__ float g_qkv[ROWS * QKVLD];

__device__ bf16 g_xh[ROWS * C_SZ], g_xl[ROWS * C_SZ];
__device__ bf16 g_yh[ROWS * C_SZ], g_yl[ROWS * C_SZ];
__device__ bf16 g_wh[QKVLD * C_SZ], g_wl[QKVLD * C_SZ];    // [Wq|Wk|Wv]^T planes
__device__ bf16 g_woh[C_SZ * C_SZ], g_wol[C_SZ * C_SZ];    // Wo^T planes

// ---------------------------------------------------------------------------
#define CP_ASYNC16(dst, src) \
    asm volatile("cp.async.cg.shared.global [%0], [%1], 16;\n" :: "r"(dst), "l"(src))

__device__ __forceinline__ unsigned cvt_tf32(float f) {
    unsigned u;
    asm("cvt.rna.tf32.f32 %0, %1;" : "=r"(u) : "f"(f));
    return u;
}

__device__ __forceinline__ uint32_t smem_u32(const void* p) {
    uint32_t a;
    asm("{ .reg .u64 t; cvta.to.shared.u64 t, %1; cvt.u32.u64 %0, t; }" : "=r"(a) : "l"(p));
    return a;
}

#define MMA_TF32(d, a, b) \
    asm volatile("mma.sync.aligned.m16n8k8.row.col.f32.tf32.tf32.f32 " \
                 "{%0,%1,%2,%3}, {%4,%5,%6,%7}, {%8,%9}, {%0,%1,%2,%3};\n" \
                 : "+f"(d[0]), "+f"(d[1]), "+f"(d[2]), "+f"(d[3]) \
                 : "r"(a[0]), "r"(a[1]), "r"(a[2]), "r"(a[3]), "r"(b[0]), "r"(b[1]))

#define MMA_BF16(d, a, b) \
    asm volatile("mma.sync.aligned.m16n8k16.row.col.f32.bf16.bf16.f32 " \
                 "{%0,%1,%2,%3}, {%4,%5,%6,%7}, {%8,%9}, {%0,%1,%2,%3};\n" \
                 : "+f"(d[0]), "+f"(d[1]), "+f"(d[2]), "+f"(d[3]) \
                 : "r"(a[0]), "r"(a[1]), "r"(a[2]), "r"(a[3]), "r"(b[0]), "r"(b[1]))

// ---------------------------------------------------------------------------
// Elementwise fp32 -> bf16 hi/lo split (for x)
// ---------------------------------------------------------------------------
__global__ void split_kernel(const float* __restrict__ x, bf16* __restrict__ hi,
                             bf16* __restrict__ lo, int n) {
    int i = blockIdx.x * blockDim.x + threadIdx.x;
    if (i >= n) return;
    float v = x[i];
    bf16 h = __float2bfloat16(v);
    hi[i] = h;
    lo[i] = __float2bfloat16(v - __bfloat162float(h));
}

// ---------------------------------------------------------------------------
// Transpose + split fused QKV weights: Wq/Wk/Wv [K][N] -> planes [3072][2048]
// ---------------------------------------------------------------------------
__global__ void tsplit_qkv(const float* __restrict__ Wq, const float* __restrict__ Wk,
                           const float* __restrict__ Wv, bf16* __restrict__ hi,
                           bf16* __restrict__ lo) {
    __shared__ float s[32][33];
    int tx = threadIdx.x, ty = threadIdx.y;     // 32 x 8
    int bx = blockIdx.x, gk = blockIdx.y * 32;
    const float* W;
    int N, nb, obase;
    if (bx < 64)      { W = Wq; N = 2048; nb = bx;      obase = 0; }
    else if (bx < 80) { W = Wk; N = 512;  nb = bx - 64; obase = 2048; }
    else              { W = Wv; N = 512;  nb = bx - 80; obase = 2560; }
    int gn = nb * 32;
#pragma unroll
    for (int j = 0; j < 4; j++)
        s[ty + j * 8][tx] = W[(size_t)(gk + ty + j * 8) * N + gn + tx];
    __syncthreads();
#pragma unroll
    for (int j = 0; j < 4; j++) {
        float v = s[tx][ty + j * 8];
        bf16 h = __float2bfloat16(v);
        size_t o = (size_t)(obase + gn + ty + j * 8) * C_SZ + gk + tx;
        hi[o] = h;
        lo[o] = __float2bfloat16(v - __bfloat162float(h));
    }
}

// Transpose + split single weight Wo [K][N] -> [N][K]
__global__ void tsplit_kernel(const float* __restrict__ W, bf16* __restrict__ hi,
                              bf16* __restrict__ lo, int K, int N) {
    __shared__ float s[32][33];
    int tx = threadIdx.x, ty = threadIdx.y;     // 32 x 8
    int gn = blockIdx.x * 32, gk = blockIdx.y * 32;
#pragma unroll
    for (int j = 0; j < 4; j++)
        s[ty + j * 8][tx] = W[(size_t)(gk + ty + j * 8) * N + gn + tx];
    __syncthreads();
#pragma unroll
    for (int j = 0; j < 4; j++) {
        float v = s[tx][ty + j * 8];
        bf16 h = __float2bfloat16(v);
        size_t o = (size_t)(gn + ty + j * 8) * K + gk + tx;
        hi[o] = h;
        lo[o] = __float2bfloat16(v - __bfloat162float(h));
    }
}

// ---------------------------------------------------------------------------
// bf16x3 tensor-core GEMM: C[M,N] = A[M,K] @ Bt[N,K]^T
// Block 128x128x32, 256 threads, warp 64x32, m16n8k16 bf16, 2-stage cp.async.
// __launch_bounds__(256, 2): 2 CTAs/SM (160KB smem, <=128 regs) so one CTA's
// barrier/LDS stalls are covered by the other's HMMA issue.
// ---------------------------------------------------------------------------
#define BBM 128
#define BBN 128
#define BBK 32
#define KSTR 40
#define BPLANE (128 * KSTR)
#define BPLANE32 (BPLANE / 2)

__global__ __launch_bounds__(256, 2) void gemm_b3(const bf16* __restrict__ Ah,
                                                  const bf16* __restrict__ Al,
                                                  const bf16* __restrict__ Bh,
                                                  const bf16* __restrict__ Bl,
                                                  float* __restrict__ C,
                                                  int M, int N, int K) {
    extern __shared__ bf16 smb[];

    int tid = threadIdx.x;
    int warp = tid >> 5, lane = tid & 31;
    int g = lane >> 2, tg = lane & 3;
    int wm = (warp & 1) * 64;
    int wn = (warp >> 1) * 32;
    int brow = blockIdx.y * BBM, bcol = blockIdx.x * BBN;

    float acc[4][4][4] = {};
    const int nK = K / BBK;

    auto loadTile = [&](int kt, int buf) {
        bf16* dstb = smb + buf * (4 * BPLANE);
#pragma unroll
        for (int i = 0; i < 8; i++) {
            int idx = tid + i * 256;
            int plane = idx >> 9;
            int rem = idx & 511;
            int row = rem >> 2, c = rem & 3;
            const bf16* src;
            if (plane == 0)      src = Ah + (size_t)(brow + row) * K;
            else if (plane == 1) src = Al + (size_t)(brow + row) * K;
            else if (plane == 2) src = Bh + (size_t)(bcol + row) * K;
            else                 src = Bl + (size_t)(bcol + row) * K;
            src += kt * BBK + c * 8;
            unsigned d = smem_u32(dstb + plane * BPLANE + row * KSTR + c * 8);
            CP_ASYNC16(d, src);
        }
        asm volatile("cp.async.commit_group;\n");
    };

    loadTile(0, 0);

    for (int kt = 0; kt < nK; kt++) {
        if (kt + 1 < nK) {
            loadTile(kt + 1, (kt + 1) & 1);
            asm volatile("cp.async.wait_group 1;\n");
        } else {
            asm volatile("cp.async.wait_group 0;\n");
        }
        __syncthreads();

        const unsigned* ah = (const unsigned*)(smb + (kt & 1) * (4 * BPLANE));
        const unsigned* al = ah + BPLANE32;
        const unsigned* bh = ah + 2 * BPLANE32;
        const unsigned* bl = ah + 3 * BPLANE32;

#pragma unroll
        for (int ks = 0; ks < 2; ks++) {
            int kc = ks * 8 + tg;
            unsigned Afh[4][4], Afl[4][4], Bfh[4][2], Bfl[4][2];
#pragma unroll
            for (int mt = 0; mt < 4; mt++) {
                int o = (wm + mt * 16 + g) * 20 + kc;
                Afh[mt][0] = ah[o];       Afh[mt][1] = ah[o + 160];
                Afh[mt][2] = ah[o + 4];   Afh[mt][3] = ah[o + 164];
                Afl[mt][0] = al[o];       Afl[mt][1] = al[o + 160];
                Afl[mt][2] = al[o + 4];   Afl[mt][3] = al[o + 164];
            }
#pragma unroll
            for (int nt = 0; nt < 4; nt++) {
                int o = (wn + nt * 8 + g) * 20 + kc;
                Bfh[nt][0] = bh[o];  Bfh[nt][1] = bh[o + 4];
                Bfl[nt][0] = bl[o];  Bfl[nt][1] = bl[o + 4];
            }
#pragma unroll
            for (int mt = 0; mt < 4; mt++)
#pragma unroll
                for (int nt = 0; nt < 4; nt++) {
                    MMA_BF16(acc[mt][nt], Afh[mt], Bfh[nt]);
                    MMA_BF16(acc[mt][nt], Afh[mt], Bfl[nt]);
                    MMA_BF16(acc[mt][nt], Afl[mt], Bfh[nt]);
                }
        }
        __syncthreads();
    }

#pragma unroll
    for (int mt = 0; mt < 4; mt++) {
        int r0 = brow + wm + mt * 16 + g;
#pragma unroll
        for (int nt = 0; nt < 4; nt++) {
            int c0 = bcol + wn + nt * 8 + tg * 2;
            *(float2*)&C[(size_t)r0 * N + c0] = make_float2(acc[mt][nt][0], acc[mt][nt][1]);
            *(float2*)&C[(size_t)(r0 + 8) * N + c0] = make_float2(acc[mt][nt][2], acc[mt][nt][3]);
        }
    }
}

// ---------------------------------------------------------------------------
// Fused RoPE + tf32-rna rounding over packed QKV.
// 48 slots: 0-31 q rope (fp32), 32-39 k rope+rna, 40-47 v rna only.
// ---------------------------------------------------------------------------
__global__ void rope_fused(float* __restrict__ qkv) {
    int idx = blockIdx.x * blockDim.x + threadIdx.x;
    int total = ROWS * 48 * 32;
    if (idx >= total) return;
    int i = idx & 31;
    int hh = (idx >> 5) % 48;
    int row = idx / (48 * 32);

    float* p;
    if (hh < 32)      p = qkv + (size_t)row * QKVLD + hh * HD;
    else if (hh < 40) p = qkv + (size_t)row * QKVLD + 2048 + (hh - 32) * HD;
    else              p = qkv + (size_t)row * QKVLD + 2560 + (hh - 40) * HD;

    if (hh >= 40) {   // v: tf32-rna round only
        p[i]      = __uint_as_float(cvt_tf32(p[i]));
        p[i + 32] = __uint_as_float(cvt_tf32(p[i + 32]));
        return;
    }

    int t = row & (T_SZ - 1);
    float invf = expf(-(float)i * 0.28782313662425574f);  // ln(10000)/32
    float ang = (float)t * invf;
    float c = cosf(ang), s = sinf(ang);

    float x0 = p[i];
    float x1 = p[i + 32];
    float r0 = x0 * c - x1 * s;
    float r1 = x1 * c + x0 * s;
    if (hh >= 32) {   // k: rope + rna round
        p[i]      = __uint_as_float(cvt_tf32(r0));
        p[i + 32] = __uint_as_float(cvt_tf32(r1));
    } else {          // q: rope, fp32
        p[i]      = r0;
        p[i + 32] = r1;
    }
}

// ---------------------------------------------------------------------------
// TF32 tensor-core flash attention (causal), fused-QKV input (stride 3072).
// Epilogue writes y directly as bf16 hi/lo planes (feeds Wo bf16x3 GEMM).
// ---------------------------------------------------------------------------
#define FQ 128
#define FK 64
#define FSTR 68
#define FBUF (FK * FSTR * 2)

__global__ __launch_bounds__(256, 2) void flash_tc(const float* __restrict__ qkv,
                                                   bf16* __restrict__ yh,
                                                   bf16* __restrict__ yl) {
    extern __shared__ float smf[];
    int qt = blockIdx.x, h = blockIdx.y, b = blockIdx.z;
    int hk = h >> 2;
    int tid = threadIdx.x, w = tid >> 5, lane = tid & 31;
    int g = lane >> 2, tg = lane & 3;
    int qbase = qt * FQ;
    size_t bT = (size_t)b * T_SZ;

    {
        const float* qg = qkv + (bT + qbase) * QKVLD + h * HD;
#pragma unroll
        for (int i = 0; i < 8; i++) {
            int idx = tid + i * 256;
            int r = idx >> 4, c4 = (idx & 15) * 4;
            unsigned d = smem_u32(smf + r * FSTR + c4);
            CP_ASYNC16(d, qg + (size_t)r * QKVLD + c4);
        }
        asm volatile("cp.async.commit_group;\ncp.async.wait_group 0;\n");
    }
    __syncthreads();

    unsigned qa[8][4];
    {
        int r0 = w * 16 + g;
#pragma unroll
        for (int c = 0; c < 8; c++) {
            qa[c][0] = cvt_tf32(smf[r0 * FSTR + 8 * c + tg] * 0.125f);
            qa[c][1] = cvt_tf32(smf[(r0 + 8) * FSTR + 8 * c + tg] * 0.125f);
            qa[c][2] = cvt_tf32(smf[r0 * FSTR + 8 * c + tg + 4] * 0.125f);
            qa[c][3] = cvt_tf32(smf[(r0 + 8) * FSTR + 8 * c + tg + 4] * 0.125f);
        }
    }
    __syncthreads();

    auto loadKV = [&](int kt, int buf) {
        float* base = smf + buf * FBUF;
        const float* kg = qkv + (bT + kt * FK) * QKVLD + 2048 + hk * HD;
        const float* vg = qkv + (bT + kt * FK) * QKVLD + 2560 + hk * HD;
#pragma unroll
        for (int i = 0; i < 4; i++) {
            int idx = tid + i * 256;
            int r = idx >> 4, c4 = (idx & 15) * 4;
            unsigned dk = smem_u32(base + r * FSTR + c4);
            CP_ASYNC16(dk, kg + (size_t)r * QKVLD + c4);
            unsigned dv = smem_u32(base + FK * FSTR + r * FSTR + c4);
            CP_ASYNC16(dv, vg + (size_t)r * QKVLD + c4);
        }
        asm volatile("cp.async.commit_group;\n");
    };

    float yacc[8][4] = {};
    float m0 = -INFINITY, m1 = -INFINITY, l0 = 0.0f, l1 = 0.0f;
    int rg0 = qbase + w * 16 + g;

    int nkt = 2 * qt + 2;
    loadKV(0, 0);

    for (int kt = 0; kt < nkt; kt++) {
        if (kt + 1 < nkt) {
            loadKV(kt + 1, (kt + 1) & 1);
            asm volatile("cp.async.wait_group 1;\n");
        } else {
            asm volatile("cp.async.wait_group 0;\n");
        }
        __syncthreads();

        bool active = (FK * kt <= qbase + 16 * w + 15);
        if (active) {
            const float* Ks = smf + (kt & 1) * FBUF;
            const float* Vs = Ks + FK * FSTR;

            float sacc[8][4] = {};
#pragma unroll
            for (int c = 0; c < 8; c++) {
#pragma unroll
                for (int nf = 0; nf < 8; nf++) {
                    unsigned bb[2];
                    bb[0] = __float_as_uint(Ks[(8 * nf + g) * FSTR + 8 * c + tg]);
                    bb[1] = __float_as_uint(Ks[(8 * nf + g) * FSTR + 8 * c + tg + 4]);
                    MMA_TF32(sacc[nf], qa[c], bb);
                }
            }

            if (kt >= 2 * qt) {
                int k0 = FK * kt;
#pragma unroll
                for (int nf = 0; nf < 8; nf++) {
                    int jg = k0 + 8 * nf + 2 * tg;
                    if (jg > rg0)     sacc[nf][0] = -INFINITY;
                    if (jg + 1 > rg0) sacc[nf][1] = -INFINITY;
                    if (jg > rg0 + 8)     sacc[nf][2] = -INFINITY;
                    if (jg + 1 > rg0 + 8) sacc[nf][3] = -INFINITY;
                }
            }

            float mt0 = -INFINITY, mt1 = -INFINITY;
#pragma unroll
            for (int nf = 0; nf < 8; nf++) {
                mt0 = fmaxf(mt0, fmaxf(sacc[nf][0], sacc[nf][1]));
                mt1 = fmaxf(mt1, fmaxf(sacc[nf][2], sacc[nf][3]));
            }
            mt0 = fmaxf(mt0, __shfl_xor_sync(0xffffffffu, mt0, 1));
            mt0 = fmaxf(mt0, __shfl_xor_sync(0xffffffffu, mt0, 2));
            mt1 = fmaxf(mt1, __shfl_xor_sync(0xffffffffu, mt1, 1));
            mt1 = fmaxf(mt1, __shfl_xor_sync(0xffffffffu, mt1, 2));

            float mn0 = fmaxf(m0, mt0), mn1 = fmaxf(m1, mt1);
            float al0 = __expf(m0 - mn0), al1 = __expf(m1 - mn1);
            m0 = mn0; m1 = mn1;
#pragma unroll
            for (int nf = 0; nf < 8; nf++) {
                yacc[nf][0] *= al0; yacc[nf][1] *= al0;
                yacc[nf][2] *= al1; yacc[nf][3] *= al1;
            }

            float pl0 = 0.0f, pl1 = 0.0f;
#pragma unroll
            for (int c = 0; c < 8; c++) {
                float p0 = __expf(sacc[c][0] - mn0);
                float p1 = __expf(sacc[c][1] - mn0);
                float p2 = __expf(sacc[c][2] - mn1);
                float p3 = __expf(sacc[c][3] - mn1);
                pl0 += p0 + p1;
                pl1 += p2 + p3;
                unsigned pa[4];
                pa[0] = cvt_tf32(p0);
                pa[1] = cvt_tf32(p2);
                pa[2] = cvt_tf32(p1);
                pa[3] = cvt_tf32(p3);
#pragma unroll
                for (int nf = 0; nf < 8; nf++) {
                    unsigned bb[2];
                    bb[0] = __float_as_uint(Vs[(8 * c + 2 * tg) * FSTR + 8 * nf + g]);
                    bb[1] = __float_as_uint(Vs[(8 * c + 2 * tg + 1) * FSTR + 8 * nf + g]);
                    MMA_TF32(yacc[nf], pa, bb);
                }
            }
            pl0 += __shfl_xor_sync(0xffffffffu, pl0, 1);
            pl0 += __shfl_xor_sync(0xffffffffu, pl0, 2);
            pl1 += __shfl_xor_sync(0xffffffffu, pl1, 1);
            pl1 += __shfl_xor_sync(0xffffffffu, pl1, 2);
            l0 = l0 * al0 + pl0;
            l1 = l1 * al1 + pl1;
        }
        __syncthreads();
    }

    // normalize + split to bf16 hi/lo planes
    float inv0 = 1.0f / l0, inv1 = 1.0f / l1;
    size_t r0 = (bT + qbase + w * 16 + g) * C_SZ + h * HD;
    size_t r1 = r0 + 8 * (size_t)C_SZ;
#pragma unroll
    for (int nf = 0; nf < 8; nf++) {
        int c0 = 8 * nf + 2 * tg;
        float v0 = yacc[nf][0] * inv0, v1 = yacc[nf][1] * inv0;
        float v2 = yacc[nf][2] * inv1, v3 = yacc[nf][3] * inv1;
        bf16 h0 = __float2bfloat16(v0), h1 = __float2bfloat16(v1);
        bf16 h2 = __float2bfloat16(v2), h3 = __float2bfloat16(v3);
        __nv_bfloat162 hp0; hp0.x = h0; hp0.y = h1;
        __nv_bfloat162 hp1; hp1.x = h2; hp1.y = h3;
        *(__nv_bfloat162*)&yh[r0 + c0] = hp0;
        *(__nv_bfloat162*)&yh[r1 + c0] = hp1;
        __nv_bfloat162 lp0, lp1;
        lp0.x = __float2bfloat16(v0 - __bfloat162float(h0));
        lp0.y = __float2bfloat16(v1 - __bfloat162float(h1));
        lp1.x = __float2bfloat16(v2 - __bfloat162float(h2));
        lp1.y = __float2bfloat16(v3 - __bfloat162float(h3));
        *(__nv_bfloat162*)&yl[r0 + c0] = lp0;
        *(__nv_bfloat162*)&yl[r1 + c0] = lp1;
    }
}

// ---------------------------------------------------------------------------
extern "C" void kernel_launch(void* const* d_in, const int* in_sizes, int n_in,
                              void* d_out, int out_size) {
    const float* x  = (const float*)d_in[0];
    const float* Wq = (const float*)d_in[1];
    const float* Wk = (const float*)d_in[2];
    const float* Wv = (const float*)d_in[3];
    const float* Wo = (const float*)d_in[4];
    float* out = (float*)d_out;

    float* pqkv;
    cudaGetSymbolAddress((void**)&pqkv, g_qkv);

    bf16 *xh, *xl, *yh, *yl, *wh, *wl, *woh, *wol;
    cudaGetSymbolAddress((void**)&xh, g_xh);  cudaGetSymbolAddress((void**)&xl, g_xl);
    cudaGetSymbolAddress((void**)&yh, g_yh);  cudaGetSymbolAddress((void**)&yl, g_yl);
    cudaGetSymbolAddress((void**)&wh, g_wh);  cudaGetSymbolAddress((void**)&wl, g_wl);
    cudaGetSymbolAddress((void**)&woh, g_woh); cudaGetSymbolAddress((void**)&wol, g_wol);

    int bsmem = 2 * 4 * BPLANE * (int)sizeof(bf16);   // 81920
    cudaFuncSetAttribute(gemm_b3, cudaFuncAttributeMaxDynamicSharedMemorySize, bsmem);
    int fsmem = 2 * FBUF * (int)sizeof(float);        // 69632
    cudaFuncSetAttribute(flash_tc, cudaFuncAttributeMaxDynamicSharedMemorySize, fsmem);

    // (0) split x; (1) fused QKV weight planes; (2) Wo planes
    {
        int n = ROWS * C_SZ;
        split_kernel<<<(n + 255) / 256, 256>>>(x, xh, xl, n);
    }
    tsplit_qkv<<<dim3(96, C_SZ / 32), dim3(32, 8)>>>(Wq, Wk, Wv, wh, wl);
    tsplit_kernel<<<dim3(C_SZ / 32, C_SZ / 32), dim3(32, 8)>>>(Wo, woh, wol, C_SZ, C_SZ);

    // (3) fused QKV projection (bf16x3, 2 CTAs/SM)
    gemm_b3<<<dim3(QKVLD / BBN, ROWS / BBM), 256, bsmem>>>(
        xh, xl, wh, wl, pqkv, ROWS, QKVLD, C_SZ);

    // (4) fused RoPE + k/v tf32-rna rounding
    {
        int tot = ROWS * 48 * 32;
        rope_fused<<<(tot + 255) / 256, 256>>>(pqkv);
    }

    // (5) flash attention (tf32) -> y bf16 hi/lo planes   <- ncu slot (-s 5)
    flash_tc<<<dim3(T_SZ / FQ, NH, B_SZ), 256, fsmem>>>(pqkv, yh, yl);

    // (6) output projection (bf16x3, 2 CTAs/SM)
    gemm_b3<<<dim3(C_SZ / BBN, ROWS / BBM), 256, bsmem>>>(
        yh, yl, woh, wol, out, ROWS, C_SZ, C_SZ);
}

// round 14
// speedup vs baseline: 2.1127x; 1.0154x over previous
#include <cuda_runtime.h>
#include <cuda_bf16.h>
#include <math.h>
#include <stdint.h>

// Problem constants
#define B_SZ 2
#define T_SZ 2048
#define C_SZ 2048
#define NH 32
#define NKV 8
#define HD 64
#define ROWS (B_SZ * T_SZ)          // 4096
#define QKVLD 3072                  // fused qkv row stride

typedef __nv_bfloat16 bf16;

// Scratch (allocation-free: __device__ globals)
__device__ float g_qkv[ROWS * QKVLD];

__device__ bf16 g_xh[ROWS * C_SZ], g_xl[ROWS * C_SZ];
__device__ bf16 g_yh[ROWS * C_SZ], g_yl[ROWS * C_SZ];
__device__ bf16 g_wh[QKVLD * C_SZ], g_wl[QKVLD * C_SZ];    // [Wq|Wk|Wv]^T planes
__device__ bf16 g_woh[C_SZ * C_SZ], g_wol[C_SZ * C_SZ];    // Wo^T planes

// ---------------------------------------------------------------------------
#define CP_ASYNC16(dst, src) \
    asm volatile("cp.async.cg.shared.global [%0], [%1], 16;\n" :: "r"(dst), "l"(src))

__device__ __forceinline__ unsigned cvt_tf32(float f) {
    unsigned u;
    asm("cvt.rna.tf32.f32 %0, %1;" : "=r"(u) : "f"(f));
    return u;
}

__device__ __forceinline__ uint32_t smem_u32(const void* p) {
    uint32_t a;
    asm("{ .reg .u64 t; cvta.to.shared.u64 t, %1; cvt.u32.u64 %0, t; }" : "=r"(a) : "l"(p));
    return a;
}

#define MMA_TF32(d, a, b) \
    asm volatile("mma.sync.aligned.m16n8k8.row.col.f32.tf32.tf32.f32 " \
                 "{%0,%1,%2,%3}, {%4,%5,%6,%7}, {%8,%9}, {%0,%1,%2,%3};\n" \
                 : "+f"(d[0]), "+f"(d[1]), "+f"(d[2]), "+f"(d[3]) \
                 : "r"(a[0]), "r"(a[1]), "r"(a[2]), "r"(a[3]), "r"(b[0]), "r"(b[1]))

#define MMA_BF16(d, a, b) \
    asm volatile("mma.sync.aligned.m16n8k16.row.col.f32.bf16.bf16.f32 " \
                 "{%0,%1,%2,%3}, {%4,%5,%6,%7}, {%8,%9}, {%0,%1,%2,%3};\n" \
                 : "+f"(d[0]), "+f"(d[1]), "+f"(d[2]), "+f"(d[3]) \
                 : "r"(a[0]), "r"(a[1]), "r"(a[2]), "r"(a[3]), "r"(b[0]), "r"(b[1]))

#define LDSM_X4(r0, r1, r2, r3, addr) \
    asm volatile("ldmatrix.sync.aligned.m8n8.x4.shared.b16 {%0,%1,%2,%3}, [%4];" \
                 : "=r"(r0), "=r"(r1), "=r"(r2), "=r"(r3) : "r"(addr))

// ---------------------------------------------------------------------------
// Elementwise fp32 -> bf16 hi/lo split (for x)
// ---------------------------------------------------------------------------
__global__ void split_kernel(const float* __restrict__ x, bf16* __restrict__ hi,
                             bf16* __restrict__ lo, int n) {
    int i = blockIdx.x * blockDim.x + threadIdx.x;
    if (i >= n) return;
    float v = x[i];
    bf16 h = __float2bfloat16(v);
    hi[i] = h;
    lo[i] = __float2bfloat16(v - __bfloat162float(h));
}

// ---------------------------------------------------------------------------
// Transpose + split fused QKV weights: Wq/Wk/Wv [K][N] -> planes [3072][2048]
// ---------------------------------------------------------------------------
__global__ void tsplit_qkv(const float* __restrict__ Wq, const float* __restrict__ Wk,
                           const float* __restrict__ Wv, bf16* __restrict__ hi,
                           bf16* __restrict__ lo) {
    __shared__ float s[32][33];
    int tx = threadIdx.x, ty = threadIdx.y;     // 32 x 8
    int bx = blockIdx.x, gk = blockIdx.y * 32;
    const float* W;
    int N, nb, obase;
    if (bx < 64)      { W = Wq; N = 2048; nb = bx;      obase = 0; }
    else if (bx < 80) { W = Wk; N = 512;  nb = bx - 64; obase = 2048; }
    else              { W = Wv; N = 512;  nb = bx - 80; obase = 2560; }
    int gn = nb * 32;
#pragma unroll
    for (int j = 0; j < 4; j++)
        s[ty + j * 8][tx] = W[(size_t)(gk + ty + j * 8) * N + gn + tx];
    __syncthreads();
#pragma unroll
    for (int j = 0; j < 4; j++) {
        float v = s[tx][ty + j * 8];
        bf16 h = __float2bfloat16(v);
        size_t o = (size_t)(obase + gn + ty + j * 8) * C_SZ + gk + tx;
        hi[o] = h;
        lo[o] = __float2bfloat16(v - __bfloat162float(h));
    }
}

// Transpose + split single weight Wo [K][N] -> [N][K]
__global__ void tsplit_kernel(const float* __restrict__ W, bf16* __restrict__ hi,
                              bf16* __restrict__ lo, int K, int N) {
    __shared__ float s[32][33];
    int tx = threadIdx.x, ty = threadIdx.y;     // 32 x 8
    int gn = blockIdx.x * 32, gk = blockIdx.y * 32;
#pragma unroll
    for (int j = 0; j < 4; j++)
        s[ty + j * 8][tx] = W[(size_t)(gk + ty + j * 8) * N + gn + tx];
    __syncthreads();
#pragma unroll
    for (int j = 0; j < 4; j++) {
        float v = s[tx][ty + j * 8];
        bf16 h = __float2bfloat16(v);
        size_t o = (size_t)(gn + ty + j * 8) * K + gk + tx;
        hi[o] = h;
        lo[o] = __float2bfloat16(v - __bfloat162float(h));
    }
}

// ---------------------------------------------------------------------------
// bf16x3 tensor-core GEMM: C[M,N] = A[M,K] @ Bt[N,K]^T
// Block 128x128x32, 256 threads, warp 64x32, m16n8k16 bf16, 2-stage cp.async,
// 2 CTAs/SM, ldmatrix.x4 fragment loads (12 LDSM vs 48 LDS per k16-step).
// Row stride 80B: 8 rows' 16B chunks tile all 32 banks -> conflict-free LDSM.
// ---------------------------------------------------------------------------
#define BBM 128
#define BBN 128
#define BBK 32
#define KSTR 40
#define BPLANE (128 * KSTR)          // bf16 elems per plane (5120)
#define PLANE_B 10240                // bytes per plane
#define STAGE_B 40960                // bytes per stage (4 planes)

__global__ __launch_bounds__(256, 2) void gemm_b3(const bf16* __restrict__ Ah,
                                                  const bf16* __restrict__ Al,
                                                  const bf16* __restrict__ Bh,
                                                  const bf16* __restrict__ Bl,
                                                  float* __restrict__ C,
                                                  int M, int N, int K) {
    extern __shared__ bf16 smb[];

    int tid = threadIdx.x;
    int warp = tid >> 5, lane = tid & 31;
    int g = lane >> 2, tg = lane & 3;
    int wm = (warp & 1) * 64;
    int wn = (warp >> 1) * 32;
    int brow = blockIdx.y * BBM, bcol = blockIdx.x * BBN;

    float acc[4][4][4] = {};
    const int nK = K / BBK;

    uint32_t sbase = smem_u32(smb);
    // per-lane ldmatrix address components (bytes)
    uint32_t a_lane = (uint32_t)(wm + (lane & 15)) * 80u + ((lane >> 4) & 1) * 16u;
    uint32_t b_lane = (uint32_t)(wn + ((lane >> 4) * 8) + (lane & 7)) * 80u
                    + ((lane >> 3) & 1) * 16u;

    auto loadTile = [&](int kt, int buf) {
        bf16* dstb = smb + buf * (4 * BPLANE);
#pragma unroll
        for (int i = 0; i < 8; i++) {
            int idx = tid + i * 256;
            int plane = idx >> 9;
            int rem = idx & 511;
            int row = rem >> 2, c = rem & 3;
            const bf16* src;
            if (plane == 0)      src = Ah + (size_t)(brow + row) * K;
            else if (plane == 1) src = Al + (size_t)(brow + row) * K;
            else if (plane == 2) src = Bh + (size_t)(bcol + row) * K;
            else                 src = Bl + (size_t)(bcol + row) * K;
            src += kt * BBK + c * 8;
            unsigned d = smem_u32(dstb + plane * BPLANE + row * KSTR + c * 8);
            CP_ASYNC16(d, src);
        }
        asm volatile("cp.async.commit_group;\n");
    };

    loadTile(0, 0);

    for (int kt = 0; kt < nK; kt++) {
        if (kt + 1 < nK) {
            loadTile(kt + 1, (kt + 1) & 1);
            asm volatile("cp.async.wait_group 1;\n");
        } else {
            asm volatile("cp.async.wait_group 0;\n");
        }
        __syncthreads();

        uint32_t stg = sbase + (kt & 1) * STAGE_B;
        uint32_t aAh = stg + a_lane;                     // A hi plane
        uint32_t aAl = aAh + PLANE_B;                    // A lo plane
        uint32_t aBh = stg + 2 * PLANE_B + b_lane;       // B hi plane
        uint32_t aBl = aBh + PLANE_B;                    // B lo plane

#pragma unroll
        for (int ks = 0; ks < 2; ks++) {
            uint32_t kb = ks * 32u;
            unsigned Afh[4][4], Afl[4][4], Bfh[4][2], Bfl[4][2];
#pragma unroll
            for (int mt = 0; mt < 4; mt++) {
                LDSM_X4(Afh[mt][0], Afh[mt][1], Afh[mt][2], Afh[mt][3],
                        aAh + mt * (16u * 80u) + kb);
                LDSM_X4(Afl[mt][0], Afl[mt][1], Afl[mt][2], Afl[mt][3],
                        aAl + mt * (16u * 80u) + kb);
            }
#pragma unroll
            for (int p = 0; p < 2; p++) {
                LDSM_X4(Bfh[2 * p][0], Bfh[2 * p][1], Bfh[2 * p + 1][0], Bfh[2 * p + 1][1],
                        aBh + p * (16u * 80u) + kb);
                LDSM_X4(Bfl[2 * p][0], Bfl[2 * p][1], Bfl[2 * p + 1][0], Bfl[2 * p + 1][1],
                        aBl + p * (16u * 80u) + kb);
            }
#pragma unroll
            for (int mt = 0; mt < 4; mt++)
#pragma unroll
                for (int nt = 0; nt < 4; nt++) {
                    MMA_BF16(acc[mt][nt], Afh[mt], Bfh[nt]);
                    MMA_BF16(acc[mt][nt], Afh[mt], Bfl[nt]);
                    MMA_BF16(acc[mt][nt], Afl[mt], Bfh[nt]);
                }
        }
        __syncthreads();
    }

#pragma unroll
    for (int mt = 0; mt < 4; mt++) {
        int r0 = brow + wm + mt * 16 + g;
#pragma unroll
        for (int nt = 0; nt < 4; nt++) {
            int c0 = bcol + wn + nt * 8 + tg * 2;
            *(float2*)&C[(size_t)r0 * N + c0] = make_float2(acc[mt][nt][0], acc[mt][nt][1]);
            *(float2*)&C[(size_t)(r0 + 8) * N + c0] = make_float2(acc[mt][nt][2], acc[mt][nt][3]);
        }
    }
}

// ---------------------------------------------------------------------------
// Fused RoPE + tf32-rna rounding over packed QKV.
// 48 slots: 0-31 q rope (fp32), 32-39 k rope+rna, 40-47 v rna only.
// ---------------------------------------------------------------------------
__global__ void rope_fused(float* __restrict__ qkv) {
    int idx = blockIdx.x * blockDim.x + threadIdx.x;
    int total = ROWS * 48 * 32;
    if (idx >= total) return;
    int i = idx & 31;
    int hh = (idx >> 5) % 48;
    int row = idx / (48 * 32);

    float* p;
    if (hh < 32)      p = qkv + (size_t)row * QKVLD + hh * HD;
    else if (hh < 40) p = qkv + (size_t)row * QKVLD + 2048 + (hh - 32) * HD;
    else              p = qkv + (size_t)row * QKVLD + 2560 + (hh - 40) * HD;

    if (hh >= 40) {   // v: tf32-rna round only
        p[i]      = __uint_as_float(cvt_tf32(p[i]));
        p[i + 32] = __uint_as_float(cvt_tf32(p[i + 32]));
        return;
    }

    int t = row & (T_SZ - 1);
    float invf = expf(-(float)i * 0.28782313662425574f);  // ln(10000)/32
    float ang = (float)t * invf;
    float c = cosf(ang), s = sinf(ang);

    float x0 = p[i];
    float x1 = p[i + 32];
    float r0 = x0 * c - x1 * s;
    float r1 = x1 * c + x0 * s;
    if (hh >= 32) {   // k: rope + rna round
        p[i]      = __uint_as_float(cvt_tf32(r0));
        p[i + 32] = __uint_as_float(cvt_tf32(r1));
    } else {          // q: rope, fp32
        p[i]      = r0;
        p[i + 32] = r1;
    }
}

// ---------------------------------------------------------------------------
// TF32 tensor-core flash attention (causal), fused-QKV input (stride 3072).
// Epilogue writes y directly as bf16 hi/lo planes (feeds Wo bf16x3 GEMM).
// ---------------------------------------------------------------------------
#define FQ 128
#define FK 64
#define FSTR 68
#define FBUF (FK * FSTR * 2)

__global__ __launch_bounds__(256, 2) void flash_tc(const float* __restrict__ qkv,
                                                   bf16* __restrict__ yh,
                                                   bf16* __restrict__ yl) {
    extern __shared__ float smf[];
    int qt = blockIdx.x, h = blockIdx.y, b = blockIdx.z;
    int hk = h >> 2;
    int tid = threadIdx.x, w = tid >> 5, lane = tid & 31;
    int g = lane >> 2, tg = lane & 3;
    int qbase = qt * FQ;
    size_t bT = (size_t)b * T_SZ;

    {
        const float* qg = qkv + (bT + qbase) * QKVLD + h * HD;
#pragma unroll
        for (int i = 0; i < 8; i++) {
            int idx = tid + i * 256;
            int r = idx >> 4, c4 = (idx & 15) * 4;
            unsigned d = smem_u32(smf + r * FSTR + c4);
            CP_ASYNC16(d, qg + (size_t)r * QKVLD + c4);
        }
        asm volatile("cp.async.commit_group;\ncp.async.wait_group 0;\n");
    }
    __syncthreads();

    unsigned qa[8][4];
    {
        int r0 = w * 16 + g;
#pragma unroll
        for (int c = 0; c < 8; c++) {
            qa[c][0] = cvt_tf32(smf[r0 * FSTR + 8 * c + tg] * 0.125f);
            qa[c][1] = cvt_tf32(smf[(r0 + 8) * FSTR + 8 * c + tg] * 0.125f);
            qa[c][2] = cvt_tf32(smf[r0 * FSTR + 8 * c + tg + 4] * 0.125f);
            qa[c][3] = cvt_tf32(smf[(r0 + 8) * FSTR + 8 * c + tg + 4] * 0.125f);
        }
    }
    __syncthreads();

    auto loadKV = [&](int kt, int buf) {
        float* base = smf + buf * FBUF;
        const float* kg = qkv + (bT + kt * FK) * QKVLD + 2048 + hk * HD;
        const float* vg = qkv + (bT + kt * FK) * QKVLD + 2560 + hk * HD;
#pragma unroll
        for (int i = 0; i < 4; i++) {
            int idx = tid + i * 256;
            int r = idx >> 4, c4 = (idx & 15) * 4;
            unsigned dk = smem_u32(base + r * FSTR + c4);
            CP_ASYNC16(dk, kg + (size_t)r * QKVLD + c4);
            unsigned dv = smem_u32(base + FK * FSTR + r * FSTR + c4);
            CP_ASYNC16(dv, vg + (size_t)r * QKVLD + c4);
        }
        asm volatile("cp.async.commit_group;\n");
    };

    float yacc[8][4] = {};
    float m0 = -INFINITY, m1 = -INFINITY, l0 = 0.0f, l1 = 0.0f;
    int rg0 = qbase + w * 16 + g;

    int nkt = 2 * qt + 2;
    loadKV(0, 0);

    for (int kt = 0; kt < nkt; kt++) {
        if (kt + 1 < nkt) {
            loadKV(kt + 1, (kt + 1) & 1);
            asm volatile("cp.async.wait_group 1;\n");
        } else {
            asm volatile("cp.async.wait_group 0;\n");
        }
        __syncthreads();

        bool active = (FK * kt <= qbase + 16 * w + 15);
        if (active) {
            const float* Ks = smf + (kt & 1) * FBUF;
            const float* Vs = Ks + FK * FSTR;

            float sacc[8][4] = {};
#pragma unroll
            for (int c = 0; c < 8; c++) {
#pragma unroll
                for (int nf = 0; nf < 8; nf++) {
                    unsigned bb[2];
                    bb[0] = __float_as_uint(Ks[(8 * nf + g) * FSTR + 8 * c + tg]);
                    bb[1] = __float_as_uint(Ks[(8 * nf + g) * FSTR + 8 * c + tg + 4]);
                    MMA_TF32(sacc[nf], qa[c], bb);
                }
            }

            if (kt >= 2 * qt) {
                int k0 = FK * kt;
#pragma unroll
                for (int nf = 0; nf < 8; nf++) {
                    int jg = k0 + 8 * nf + 2 * tg;
                    if (jg > rg0)     sacc[nf][0] = -INFINITY;
                    if (jg + 1 > rg0) sacc[nf][1] = -INFINITY;
                    if (jg > rg0 + 8)     sacc[nf][2] = -INFINITY;
                    if (jg + 1 > rg0 + 8) sacc[nf][3] = -INFINITY;
                }
            }

            float mt0 = -INFINITY, mt1 = -INFINITY;
#pragma unroll
            for (int nf = 0; nf < 8; nf++) {
                mt0 = fmaxf(mt0, fmaxf(sacc[nf][0], sacc[nf][1]));
                mt1 = fmaxf(mt1, fmaxf(sacc[nf][2], sacc[nf][3]));
            }
            mt0 = fmaxf(mt0, __shfl_xor_sync(0xffffffffu, mt0, 1));
            mt0 = fmaxf(mt0, __shfl_xor_sync(0xffffffffu, mt0, 2));
            mt1 = fmaxf(mt1, __shfl_xor_sync(0xffffffffu, mt1, 1));
            mt1 = fmaxf(mt1, __shfl_xor_sync(0xffffffffu, mt1, 2));

            float mn0 = fmaxf(m0, mt0), mn1 = fmaxf(m1, mt1);
            float al0 = __expf(m0 - mn0), al1 = __expf(m1 - mn1);
            m0 = mn0; m1 = mn1;
#pragma unroll
            for (int nf = 0; nf < 8; nf++) {
                yacc[nf][0] *= al0; yacc[nf][1] *= al0;
                yacc[nf][2] *= al1; yacc[nf][3] *= al1;
            }

            float pl0 = 0.0f, pl1 = 0.0f;
#pragma unroll
            for (int c = 0; c < 8; c++) {
                float p0 = __expf(sacc[c][0] - mn0);
                float p1 = __expf(sacc[c][1] - mn0);
                float p2 = __expf(sacc[c][2] - mn1);
                float p3 = __expf(sacc[c][3] - mn1);
                pl0 += p0 + p1;
                pl1 += p2 + p3;
                unsigned pa[4];
                pa[0] = cvt_tf32(p0);
                pa[1] = cvt_tf32(p2);
                pa[2] = cvt_tf32(p1);
                pa[3] = cvt_tf32(p3);
#pragma unroll
                for (int nf = 0; nf < 8; nf++) {
                    unsigned bb[2];
                    bb[0] = __float_as_uint(Vs[(8 * c + 2 * tg) * FSTR + 8 * nf + g]);
                    bb[1] = __float_as_uint(Vs[(8 * c + 2 * tg + 1) * FSTR + 8 * nf + g]);
                    MMA_TF32(yacc[nf], pa, bb);
                }
            }
            pl0 += __shfl_xor_sync(0xffffffffu, pl0, 1);
            pl0 += __shfl_xor_sync(0xffffffffu, pl0, 2);
            pl1 += __shfl_xor_sync(0xffffffffu, pl1, 1);
            pl1 += __shfl_xor_sync(0xffffffffu, pl1, 2);
            l0 = l0 * al0 + pl0;
            l1 = l1 * al1 + pl1;
        }
        __syncthreads();
    }

    // normalize + split to bf16 hi/lo planes
    float inv0 = 1.0f / l0, inv1 = 1.0f / l1;
    size_t r0 = (bT + qbase + w * 16 + g) * C_SZ + h * HD;
    size_t r1 = r0 + 8 * (size_t)C_SZ;
#pragma unroll
    for (int nf = 0; nf < 8; nf++) {
        int c0 = 8 * nf + 2 * tg;
        float v0 = yacc[nf][0] * inv0, v1 = yacc[nf][1] * inv0;
        float v2 = yacc[nf][2] * inv1, v3 = yacc[nf][3] * inv1;
        bf16 h0 = __float2bfloat16(v0), h1 = __float2bfloat16(v1);
        bf16 h2 = __float2bfloat16(v2), h3 = __float2bfloat16(v3);
        __nv_bfloat162 hp0; hp0.x = h0; hp0.y = h1;
        __nv_bfloat162 hp1; hp1.x = h2; hp1.y = h3;
        *(__nv_bfloat162*)&yh[r0 + c0] = hp0;
        *(__nv_bfloat162*)&yh[r1 + c0] = hp1;
        __nv_bfloat162 lp0, lp1;
        lp0.x = __float2bfloat16(v0 - __bfloat162float(h0));
        lp0.y = __float2bfloat16(v1 - __bfloat162float(h1));
        lp1.x = __float2bfloat16(v2 - __bfloat162float(h2));
        lp1.y = __float2bfloat16(v3 - __bfloat162float(h3));
        *(__nv_bfloat162*)&yl[r0 + c0] = lp0;
        *(__nv_bfloat162*)&yl[r1 + c0] = lp1;
    }
}

// ---------------------------------------------------------------------------
extern "C" void kernel_launch(void* const* d_in, const int* in_sizes, int n_in,
                              void* d_out, int out_size) {
    const float* x  = (const float*)d_in[0];
    const float* Wq = (const float*)d_in[1];
    const float* Wk = (const float*)d_in[2];
    const float* Wv = (const float*)d_in[3];
    const float* Wo = (const float*)d_in[4];
    float* out = (float*)d_out;

    float* pqkv;
    cudaGetSymbolAddress((void**)&pqkv, g_qkv);

    bf16 *xh, *xl, *yh, *yl, *wh, *wl, *woh, *wol;
    cudaGetSymbolAddress((void**)&xh, g_xh);  cudaGetSymbolAddress((void**)&xl, g_xl);
    cudaGetSymbolAddress((void**)&yh, g_yh);  cudaGetSymbolAddress((void**)&yl, g_yl);
    cudaGetSymbolAddress((void**)&wh, g_wh);  cudaGetSymbolAddress((void**)&wl, g_wl);
    cudaGetSymbolAddress((void**)&woh, g_woh); cudaGetSymbolAddress((void**)&wol, g_wol);

    int bsmem = 2 * STAGE_B;                          // 81920
    cudaFuncSetAttribute(gemm_b3, cudaFuncAttributeMaxDynamicSharedMemorySize, bsmem);
    int fsmem = 2 * FBUF * (int)sizeof(float);        // 69632
    cudaFuncSetAttribute(flash_tc, cudaFuncAttributeMaxDynamicSharedMemorySize, fsmem);

    // (0) split x; (1) fused QKV weight planes; (2) Wo planes
    {
        int n = ROWS * C_SZ;
        split_kernel<<<(n + 255) / 256, 256>>>(x, xh, xl, n);
    }
    tsplit_qkv<<<dim3(96, C_SZ / 32), dim3(32, 8)>>>(Wq, Wk, Wv, wh, wl);
    tsplit_kernel<<<dim3(C_SZ / 32, C_SZ / 32), dim3(32, 8)>>>(Wo, woh, wol, C_SZ, C_SZ);

    // (3) fused QKV projection (bf16x3, 2 CTAs/SM, ldmatrix)
    gemm_b3<<<dim3(QKVLD / BBN, ROWS / BBM), 256, bsmem>>>(
        xh, xl, wh, wl, pqkv, ROWS, QKVLD, C_SZ);

    // (4) fused RoPE + k/v tf32-rna rounding
    {
        int tot = ROWS * 48 * 32;
        rope_fused<<<(tot + 255) / 256, 256>>>(pqkv);
    }

    // (5) flash attention (tf32) -> y bf16 hi/lo planes   <- ncu slot (-s 5)
    flash_tc<<<dim3(T_SZ / FQ, NH, B_SZ), 256, fsmem>>>(pqkv, yh, yl);

    // (6) output projection (bf16x3, 2 CTAs/SM, ldmatrix)
    gemm_b3<<<dim3(C_SZ / BBN, ROWS / BBM), 256, bsmem>>>(
        yh, yl, woh, wol, out, ROWS, C_SZ, C_SZ);
}

// round 15
// speedup vs baseline: 2.1187x; 1.0029x over previous
#include <cuda_runtime.h>
#include <cuda_bf16.h>
#include <math.h>
#include <stdint.h>

// Problem constants
#define B_SZ 2
#define T_SZ 2048
#define C_SZ 2048
#define NH 32
#define NKV 8
#define HD 64
#define ROWS (B_SZ * T_SZ)          // 4096
#define QKVLD 3072                  // fused qkv row stride

typedef __nv_bfloat16 bf16;

// Scratch (allocation-free: __device__ globals)
__device__ float g_qkv[ROWS * QKVLD];

__device__ bf16 g_xh[ROWS * C_SZ], g_xl[ROWS * C_SZ];
__device__ bf16 g_yh[ROWS * C_SZ], g_yl[ROWS * C_SZ];
__device__ bf16 g_wh[QKVLD * C_SZ], g_wl[QKVLD * C_SZ];    // [Wq|Wk|Wv]^T planes
__device__ bf16 g_woh[C_SZ * C_SZ], g_wol[C_SZ * C_SZ];    // Wo^T planes

// ---------------------------------------------------------------------------
#define CP_ASYNC16(dst, src) \
    asm volatile("cp.async.cg.shared.global [%0], [%1], 16;\n" :: "r"(dst), "l"(src))

__device__ __forceinline__ unsigned cvt_tf32(float f) {
    unsigned u;
    asm("cvt.rna.tf32.f32 %0, %1;" : "=r"(u) : "f"(f));
    return u;
}

__device__ __forceinline__ uint32_t smem_u32(const void* p) {
    uint32_t a;
    asm("{ .reg .u64 t; cvta.to.shared.u64 t, %1; cvt.u32.u64 %0, t; }" : "=r"(a) : "l"(p));
    return a;
}

#define MMA_TF32(d, a, b) \
    asm volatile("mma.sync.aligned.m16n8k8.row.col.f32.tf32.tf32.f32 " \
                 "{%0,%1,%2,%3}, {%4,%5,%6,%7}, {%8,%9}, {%0,%1,%2,%3};\n" \
                 : "+f"(d[0]), "+f"(d[1]), "+f"(d[2]), "+f"(d[3]) \
                 : "r"(a[0]), "r"(a[1]), "r"(a[2]), "r"(a[3]), "r"(b[0]), "r"(b[1]))

#define MMA_BF16(d, a, b) \
    asm volatile("mma.sync.aligned.m16n8k16.row.col.f32.bf16.bf16.f32 " \
                 "{%0,%1,%2,%3}, {%4,%5,%6,%7}, {%8,%9}, {%0,%1,%2,%3};\n" \
                 : "+f"(d[0]), "+f"(d[1]), "+f"(d[2]), "+f"(d[3]) \
                 : "r"(a[0]), "r"(a[1]), "r"(a[2]), "r"(a[3]), "r"(b[0]), "r"(b[1]))

#define LDSM_X4(r0, r1, r2, r3, addr) \
    asm volatile("ldmatrix.sync.aligned.m8n8.x4.shared.b16 {%0,%1,%2,%3}, [%4];" \
                 : "=r"(r0), "=r"(r1), "=r"(r2), "=r"(r3) : "r"(addr))

// ---------------------------------------------------------------------------
// Elementwise fp32 -> bf16 hi/lo split (for x)
// ---------------------------------------------------------------------------
__global__ void split_kernel(const float* __restrict__ x, bf16* __restrict__ hi,
                             bf16* __restrict__ lo, int n) {
    int i = blockIdx.x * blockDim.x + threadIdx.x;
    if (i >= n) return;
    float v = x[i];
    bf16 h = __float2bfloat16(v);
    hi[i] = h;
    lo[i] = __float2bfloat16(v - __bfloat162float(h));
}

// ---------------------------------------------------------------------------
// Transpose + split fused QKV weights: Wq/Wk/Wv [K][N] -> planes [3072][2048]
// ---------------------------------------------------------------------------
__global__ void tsplit_qkv(const float* __restrict__ Wq, const float* __restrict__ Wk,
                           const float* __restrict__ Wv, bf16* __restrict__ hi,
                           bf16* __restrict__ lo) {
    __shared__ float s[32][33];
    int tx = threadIdx.x, ty = threadIdx.y;     // 32 x 8
    int bx = blockIdx.x, gk = blockIdx.y * 32;
    const float* W;
    int N, nb, obase;
    if (bx < 64)      { W = Wq; N = 2048; nb = bx;      obase = 0; }
    else if (bx < 80) { W = Wk; N = 512;  nb = bx - 64; obase = 2048; }
    else              { W = Wv; N = 512;  nb = bx - 80; obase = 2560; }
    int gn = nb * 32;
#pragma unroll
    for (int j = 0; j < 4; j++)
        s[ty + j * 8][tx] = W[(size_t)(gk + ty + j * 8) * N + gn + tx];
    __syncthreads();
#pragma unroll
    for (int j = 0; j < 4; j++) {
        float v = s[tx][ty + j * 8];
        bf16 h = __float2bfloat16(v);
        size_t o = (size_t)(obase + gn + ty + j * 8) * C_SZ + gk + tx;
        hi[o] = h;
        lo[o] = __float2bfloat16(v - __bfloat162float(h));
    }
}

// Transpose + split single weight Wo [K][N] -> [N][K]
__global__ void tsplit_kernel(const float* __restrict__ W, bf16* __restrict__ hi,
                              bf16* __restrict__ lo, int K, int N) {
    __shared__ float s[32][33];
    int tx = threadIdx.x, ty = threadIdx.y;     // 32 x 8
    int gn = blockIdx.x * 32, gk = blockIdx.y * 32;
#pragma unroll
    for (int j = 0; j < 4; j++)
        s[ty + j * 8][tx] = W[(size_t)(gk + ty + j * 8) * N + gn + tx];
    __syncthreads();
#pragma unroll
    for (int j = 0; j < 4; j++) {
        float v = s[tx][ty + j * 8];
        bf16 h = __float2bfloat16(v);
        size_t o = (size_t)(gn + ty + j * 8) * K + gk + tx;
        hi[o] = h;
        lo[o] = __float2bfloat16(v - __bfloat162float(h));
    }
}

// ---------------------------------------------------------------------------
// bf16x3 tensor-core GEMM: C[M,N] = A[M,K] @ Bt[N,K]^T
// Block 128x128x32, 256 threads, warp 64x32, m16n8k16 bf16, 2-stage cp.async,
// 2 CTAs/SM, ldmatrix.x4 loads. MMA loops are PRODUCT-FIRST (hh, hl, lh passes)
// so same-accumulator MMAs are 16 instructions apart (no RAW latency chain);
// per-accumulator add order unchanged (hh -> hl -> lh): bit-identical.
// ---------------------------------------------------------------------------
#define BBM 128
#define BBN 128
#define BBK 32
#define KSTR 40
#define BPLANE (128 * KSTR)          // bf16 elems per plane (5120)
#define PLANE_B 10240                // bytes per plane
#define STAGE_B 40960                // bytes per stage (4 planes)

__global__ __launch_bounds__(256, 2) void gemm_b3(const bf16* __restrict__ Ah,
                                                  const bf16* __restrict__ Al,
                                                  const bf16* __restrict__ Bh,
                                                  const bf16* __restrict__ Bl,
                                                  float* __restrict__ C,
                                                  int M, int N, int K) {
    extern __shared__ bf16 smb[];

    int tid = threadIdx.x;
    int warp = tid >> 5, lane = tid & 31;
    int g = lane >> 2, tg = lane & 3;
    int wm = (warp & 1) * 64;
    int wn = (warp >> 1) * 32;
    int brow = blockIdx.y * BBM, bcol = blockIdx.x * BBN;

    float acc[4][4][4] = {};
    const int nK = K / BBK;

    uint32_t sbase = smem_u32(smb);
    uint32_t a_lane = (uint32_t)(wm + (lane & 15)) * 80u + ((lane >> 4) & 1) * 16u;
    uint32_t b_lane = (uint32_t)(wn + ((lane >> 4) * 8) + (lane & 7)) * 80u
                    + ((lane >> 3) & 1) * 16u;

    auto loadTile = [&](int kt, int buf) {
        bf16* dstb = smb + buf * (4 * BPLANE);
#pragma unroll
        for (int i = 0; i < 8; i++) {
            int idx = tid + i * 256;
            int plane = idx >> 9;
            int rem = idx & 511;
            int row = rem >> 2, c = rem & 3;
            const bf16* src;
            if (plane == 0)      src = Ah + (size_t)(brow + row) * K;
            else if (plane == 1) src = Al + (size_t)(brow + row) * K;
            else if (plane == 2) src = Bh + (size_t)(bcol + row) * K;
            else                 src = Bl + (size_t)(bcol + row) * K;
            src += kt * BBK + c * 8;
            unsigned d = smem_u32(dstb + plane * BPLANE + row * KSTR + c * 8);
            CP_ASYNC16(d, src);
        }
        asm volatile("cp.async.commit_group;\n");
    };

    loadTile(0, 0);

    for (int kt = 0; kt < nK; kt++) {
        if (kt + 1 < nK) {
            loadTile(kt + 1, (kt + 1) & 1);
            asm volatile("cp.async.wait_group 1;\n");
        } else {
            asm volatile("cp.async.wait_group 0;\n");
        }
        __syncthreads();

        uint32_t stg = sbase + (kt & 1) * STAGE_B;
        uint32_t aAh = stg + a_lane;
        uint32_t aAl = aAh + PLANE_B;
        uint32_t aBh = stg + 2 * PLANE_B + b_lane;
        uint32_t aBl = aBh + PLANE_B;

#pragma unroll
        for (int ks = 0; ks < 2; ks++) {
            uint32_t kb = ks * 32u;
            unsigned Afh[4][4], Afl[4][4], Bfh[4][2], Bfl[4][2];
#pragma unroll
            for (int mt = 0; mt < 4; mt++) {
                LDSM_X4(Afh[mt][0], Afh[mt][1], Afh[mt][2], Afh[mt][3],
                        aAh + mt * (16u * 80u) + kb);
                LDSM_X4(Afl[mt][0], Afl[mt][1], Afl[mt][2], Afl[mt][3],
                        aAl + mt * (16u * 80u) + kb);
            }
#pragma unroll
            for (int p = 0; p < 2; p++) {
                LDSM_X4(Bfh[2 * p][0], Bfh[2 * p][1], Bfh[2 * p + 1][0], Bfh[2 * p + 1][1],
                        aBh + p * (16u * 80u) + kb);
                LDSM_X4(Bfl[2 * p][0], Bfl[2 * p][1], Bfl[2 * p + 1][0], Bfl[2 * p + 1][1],
                        aBl + p * (16u * 80u) + kb);
            }
            // product-first passes: same acc touched every 16 MMAs
#pragma unroll
            for (int mt = 0; mt < 4; mt++)
#pragma unroll
                for (int nt = 0; nt < 4; nt++)
                    MMA_BF16(acc[mt][nt], Afh[mt], Bfh[nt]);
#pragma unroll
            for (int mt = 0; mt < 4; mt++)
#pragma unroll
                for (int nt = 0; nt < 4; nt++)
                    MMA_BF16(acc[mt][nt], Afh[mt], Bfl[nt]);
#pragma unroll
            for (int mt = 0; mt < 4; mt++)
#pragma unroll
                for (int nt = 0; nt < 4; nt++)
                    MMA_BF16(acc[mt][nt], Afl[mt], Bfh[nt]);
        }
        __syncthreads();
    }

#pragma unroll
    for (int mt = 0; mt < 4; mt++) {
        int r0 = brow + wm + mt * 16 + g;
#pragma unroll
        for (int nt = 0; nt < 4; nt++) {
            int c0 = bcol + wn + nt * 8 + tg * 2;
            *(float2*)&C[(size_t)r0 * N + c0] = make_float2(acc[mt][nt][0], acc[mt][nt][1]);
            *(float2*)&C[(size_t)(r0 + 8) * N + c0] = make_float2(acc[mt][nt][2], acc[mt][nt][3]);
        }
    }
}

// ---------------------------------------------------------------------------
// Fused RoPE + tf32-rna rounding over packed QKV.
// 48 slots: 0-31 q rope (fp32), 32-39 k rope+rna, 40-47 v rna only.
// ---------------------------------------------------------------------------
__global__ void rope_fused(float* __restrict__ qkv) {
    int idx = blockIdx.x * blockDim.x + threadIdx.x;
    int total = ROWS * 48 * 32;
    if (idx >= total) return;
    int i = idx & 31;
    int hh = (idx >> 5) % 48;
    int row = idx / (48 * 32);

    float* p;
    if (hh < 32)      p = qkv + (size_t)row * QKVLD + hh * HD;
    else if (hh < 40) p = qkv + (size_t)row * QKVLD + 2048 + (hh - 32) * HD;
    else              p = qkv + (size_t)row * QKVLD + 2560 + (hh - 40) * HD;

    if (hh >= 40) {   // v: tf32-rna round only
        p[i]      = __uint_as_float(cvt_tf32(p[i]));
        p[i + 32] = __uint_as_float(cvt_tf32(p[i + 32]));
        return;
    }

    int t = row & (T_SZ - 1);
    float invf = expf(-(float)i * 0.28782313662425574f);  // ln(10000)/32
    float ang = (float)t * invf;
    float c = cosf(ang), s = sinf(ang);

    float x0 = p[i];
    float x1 = p[i + 32];
    float r0 = x0 * c - x1 * s;
    float r1 = x1 * c + x0 * s;
    if (hh >= 32) {   // k: rope + rna round
        p[i]      = __uint_as_float(cvt_tf32(r0));
        p[i + 32] = __uint_as_float(cvt_tf32(r1));
    } else {          // q: rope, fp32
        p[i]      = r0;
        p[i + 32] = r1;
    }
}

// ---------------------------------------------------------------------------
// TF32 tensor-core flash attention (causal), fused-QKV input (stride 3072).
// Epilogue writes y directly as bf16 hi/lo planes (feeds Wo bf16x3 GEMM).
// ---------------------------------------------------------------------------
#define FQ 128
#define FK 64
#define FSTR 68
#define FBUF (FK * FSTR * 2)

__global__ __launch_bounds__(256, 2) void flash_tc(const float* __restrict__ qkv,
                                                   bf16* __restrict__ yh,
                                                   bf16* __restrict__ yl) {
    extern __shared__ float smf[];
    int qt = blockIdx.x, h = blockIdx.y, b = blockIdx.z;
    int hk = h >> 2;
    int tid = threadIdx.x, w = tid >> 5, lane = tid & 31;
    int g = lane >> 2, tg = lane & 3;
    int qbase = qt * FQ;
    size_t bT = (size_t)b * T_SZ;

    {
        const float* qg = qkv + (bT + qbase) * QKVLD + h * HD;
#pragma unroll
        for (int i = 0; i < 8; i++) {
            int idx = tid + i * 256;
            int r = idx >> 4, c4 = (idx & 15) * 4;
            unsigned d = smem_u32(smf + r * FSTR + c4);
            CP_ASYNC16(d, qg + (size_t)r * QKVLD + c4);
        }
        asm volatile("cp.async.commit_group;\ncp.async.wait_group 0;\n");
    }
    __syncthreads();

    unsigned qa[8][4];
    {
        int r0 = w * 16 + g;
#pragma unroll
        for (int c = 0; c < 8; c++) {
            qa[c][0] = cvt_tf32(smf[r0 * FSTR + 8 * c + tg] * 0.125f);
            qa[c][1] = cvt_tf32(smf[(r0 + 8) * FSTR + 8 * c + tg] * 0.125f);
            qa[c][2] = cvt_tf32(smf[r0 * FSTR + 8 * c + tg + 4] * 0.125f);
            qa[c][3] = cvt_tf32(smf[(r0 + 8) * FSTR + 8 * c + tg + 4] * 0.125f);
        }
    }
    __syncthreads();

    auto loadKV = [&](int kt, int buf) {
        float* base = smf + buf * FBUF;
        const float* kg = qkv + (bT + kt * FK) * QKVLD + 2048 + hk * HD;
        const float* vg = qkv + (bT + kt * FK) * QKVLD + 2560 + hk * HD;
#pragma unroll
        for (int i = 0; i < 4; i++) {
            int idx = tid + i * 256;
            int r = idx >> 4, c4 = (idx & 15) * 4;
            unsigned dk = smem_u32(base + r * FSTR + c4);
            CP_ASYNC16(dk, kg + (size_t)r * QKVLD + c4);
            unsigned dv = smem_u32(base + FK * FSTR + r * FSTR + c4);
            CP_ASYNC16(dv, vg + (size_t)r * QKVLD + c4);
        }
        asm volatile("cp.async.commit_group;\n");
    };

    float yacc[8][4] = {};
    float m0 = -INFINITY, m1 = -INFINITY, l0 = 0.0f, l1 = 0.0f;
    int rg0 = qbase + w * 16 + g;

    int nkt = 2 * qt + 2;
    loadKV(0, 0);

    for (int kt = 0; kt < nkt; kt++) {
        if (kt + 1 < nkt) {
            loadKV(kt + 1, (kt + 1) & 1);
            asm volatile("cp.async.wait_group 1;\n");
        } else {
            asm volatile("cp.async.wait_group 0;\n");
        }
        __syncthreads();

        bool active = (FK * kt <= qbase + 16 * w + 15);
        if (active) {
            const float* Ks = smf + (kt & 1) * FBUF;
            const float* Vs = Ks + FK * FSTR;

            float sacc[8][4] = {};
#pragma unroll
            for (int c = 0; c < 8; c++) {
#pragma unroll
                for (int nf = 0; nf < 8; nf++) {
                    unsigned bb[2];
                    bb[0] = __float_as_uint(Ks[(8 * nf + g) * FSTR + 8 * c + tg]);
                    bb[1] = __float_as_uint(Ks[(8 * nf + g) * FSTR + 8 * c + tg + 4]);
                    MMA_TF32(sacc[nf], qa[c], bb);
                }
            }

            if (kt >= 2 * qt) {
                int k0 = FK * kt;
#pragma unroll
                for (int nf = 0; nf < 8; nf++) {
                    int jg = k0 + 8 * nf + 2 * tg;
                    if (jg > rg0)     sacc[nf][0] = -INFINITY;
                    if (jg + 1 > rg0) sacc[nf][1] = -INFINITY;
                    if (jg > rg0 + 8)     sacc[nf][2] = -INFINITY;
                    if (jg + 1 > rg0 + 8) sacc[nf][3] = -INFINITY;
                }
            }

            float mt0 = -INFINITY, mt1 = -INFINITY;
#pragma unroll
            for (int nf = 0; nf < 8; nf++) {
                mt0 = fmaxf(mt0, fmaxf(sacc[nf][0], sacc[nf][1]));
                mt1 = fmaxf(mt1, fmaxf(sacc[nf][2], sacc[nf][3]));
            }
            mt0 = fmaxf(mt0, __shfl_xor_sync(0xffffffffu, mt0, 1));
            mt0 = fmaxf(mt0, __shfl_xor_sync(0xffffffffu, mt0, 2));
            mt1 = fmaxf(mt1, __shfl_xor_sync(0xffffffffu, mt1, 1));
            mt1 = fmaxf(mt1, __shfl_xor_sync(0xffffffffu, mt1, 2));

            float mn0 = fmaxf(m0, mt0), mn1 = fmaxf(m1, mt1);
            float al0 = __expf(m0 - mn0), al1 = __expf(m1 - mn1);
            m0 = mn0; m1 = mn1;
#pragma unroll
            for (int nf = 0; nf < 8; nf++) {
                yacc[nf][0] *= al0; yacc[nf][1] *= al0;
                yacc[nf][2] *= al1; yacc[nf][3] *= al1;
            }

            float pl0 = 0.0f, pl1 = 0.0f;
#pragma unroll
            for (int c = 0; c < 8; c++) {
                float p0 = __expf(sacc[c][0] - mn0);
                float p1 = __expf(sacc[c][1] - mn0);
                float p2 = __expf(sacc[c][2] - mn1);
                float p3 = __expf(sacc[c][3] - mn1);
                pl0 += p0 + p1;
                pl1 += p2 + p3;
                unsigned pa[4];
                pa[0] = cvt_tf32(p0);
                pa[1] = cvt_tf32(p2);
                pa[2] = cvt_tf32(p1);
                pa[3] = cvt_tf32(p3);
#pragma unroll
                for (int nf = 0; nf < 8; nf++) {
                    unsigned bb[2];
                    bb[0] = __float_as_uint(Vs[(8 * c + 2 * tg) * FSTR + 8 * nf + g]);
                    bb[1] = __float_as_uint(Vs[(8 * c + 2 * tg + 1) * FSTR + 8 * nf + g]);
                    MMA_TF32(yacc[nf], pa, bb);
                }
            }
            pl0 += __shfl_xor_sync(0xffffffffu, pl0, 1);
            pl0 += __shfl_xor_sync(0xffffffffu, pl0, 2);
            pl1 += __shfl_xor_sync(0xffffffffu, pl1, 1);
            pl1 += __shfl_xor_sync(0xffffffffu, pl1, 2);
            l0 = l0 * al0 + pl0;
            l1 = l1 * al1 + pl1;
        }
        __syncthreads();
    }

    // normalize + split to bf16 hi/lo planes
    float inv0 = 1.0f / l0, inv1 = 1.0f / l1;
    size_t r0 = (bT + qbase + w * 16 + g) * C_SZ + h * HD;
    size_t r1 = r0 + 8 * (size_t)C_SZ;
#pragma unroll
    for (int nf = 0; nf < 8; nf++) {
        int c0 = 8 * nf + 2 * tg;
        float v0 = yacc[nf][0] * inv0, v1 = yacc[nf][1] * inv0;
        float v2 = yacc[nf][2] * inv1, v3 = yacc[nf][3] * inv1;
        bf16 h0 = __float2bfloat16(v0), h1 = __float2bfloat16(v1);
        bf16 h2 = __float2bfloat16(v2), h3 = __float2bfloat16(v3);
        __nv_bfloat162 hp0; hp0.x = h0; hp0.y = h1;
        __nv_bfloat162 hp1; hp1.x = h2; hp1.y = h3;
        *(__nv_bfloat162*)&yh[r0 + c0] = hp0;
        *(__nv_bfloat162*)&yh[r1 + c0] = hp1;
        __nv_bfloat162 lp0, lp1;
        lp0.x = __float2bfloat16(v0 - __bfloat162float(h0));
        lp0.y = __float2bfloat16(v1 - __bfloat162float(h1));
        lp1.x = __float2bfloat16(v2 - __bfloat162float(h2));
        lp1.y = __float2bfloat16(v3 - __bfloat162float(h3));
        *(__nv_bfloat162*)&yl[r0 + c0] = lp0;
        *(__nv_bfloat162*)&yl[r1 + c0] = lp1;
    }
}

// ---------------------------------------------------------------------------
extern "C" void kernel_launch(void* const* d_in, const int* in_sizes, int n_in,
                              void* d_out, int out_size) {
    const float* x  = (const float*)d_in[0];
    const float* Wq = (const float*)d_in[1];
    const float* Wk = (const float*)d_in[2];
    const float* Wv = (const float*)d_in[3];
    const float* Wo = (const float*)d_in[4];
    float* out = (float*)d_out;

    float* pqkv;
    cudaGetSymbolAddress((void**)&pqkv, g_qkv);

    bf16 *xh, *xl, *yh, *yl, *wh, *wl, *woh, *wol;
    cudaGetSymbolAddress((void**)&xh, g_xh);  cudaGetSymbolAddress((void**)&xl, g_xl);
    cudaGetSymbolAddress((void**)&yh, g_yh);  cudaGetSymbolAddress((void**)&yl, g_yl);
    cudaGetSymbolAddress((void**)&wh, g_wh);  cudaGetSymbolAddress((void**)&wl, g_wl);
    cudaGetSymbolAddress((void**)&woh, g_woh); cudaGetSymbolAddress((void**)&wol, g_wol);

    int bsmem = 2 * STAGE_B;                          // 81920
    cudaFuncSetAttribute(gemm_b3, cudaFuncAttributeMaxDynamicSharedMemorySize, bsmem);
    int fsmem = 2 * FBUF * (int)sizeof(float);        // 69632
    cudaFuncSetAttribute(flash_tc, cudaFuncAttributeMaxDynamicSharedMemorySize, fsmem);

    // (0) split x; (1) fused QKV weight planes; (2) Wo planes
    {
        int n = ROWS * C_SZ;
        split_kernel<<<(n + 255) / 256, 256>>>(x, xh, xl, n);
    }
    tsplit_qkv<<<dim3(96, C_SZ / 32), dim3(32, 8)>>>(Wq, Wk, Wv, wh, wl);
    tsplit_kernel<<<dim3(C_SZ / 32, C_SZ / 32), dim3(32, 8)>>>(Wo, woh, wol, C_SZ, C_SZ);

    // (3) fused QKV projection (bf16x3, product-first MMA order)
    gemm_b3<<<dim3(QKVLD / BBN, ROWS / BBM), 256, bsmem>>>(
        xh, xl, wh, wl, pqkv, ROWS, QKVLD, C_SZ);

    // (4) fused RoPE + k/v tf32-rna rounding
    {
        int tot = ROWS * 48 * 32;
        rope_fused<<<(tot + 255) / 256, 256>>>(pqkv);
    }

    // (5) flash attention (tf32) -> y bf16 hi/lo planes   <- ncu slot (-s 5)
    flash_tc<<<dim3(T_SZ / FQ, NH, B_SZ), 256, fsmem>>>(pqkv, yh, yl);

    // (6) output projection (bf16x3, product-first MMA order)
    gemm_b3<<<dim3(C_SZ / BBN, ROWS / BBM), 256, bsmem>>>(
        yh, yl, woh, wol, out, ROWS, C_SZ, C_SZ);
}

// round 16
// speedup vs baseline: 2.8168x; 1.3295x over previous
#include <cuda_runtime.h>
#include <cuda_bf16.h>
#include <cuda_fp16.h>
#include <math.h>
#include <stdint.h>

// Problem constants
#define B_SZ 2
#define T_SZ 2048
#define C_SZ 2048
#define NH 32
#define NKV 8
#define HD 64
#define ROWS (B_SZ * T_SZ)          // 4096
#define QKVLD 3072                  // fused qkv row stride

typedef __half fp16;

// Scratch (allocation-free: __device__ globals)
__device__ float g_qkv[ROWS * QKVLD];

__device__ fp16 g_x16[ROWS * C_SZ];                        // x as fp16 (single)
__device__ fp16 g_y16[ROWS * C_SZ];                        // y as fp16 (single)
__device__ fp16 g_wh[QKVLD * C_SZ], g_wl[QKVLD * C_SZ];    // [Wq|Wk|Wv]^T fp16 limbs
__device__ fp16 g_woh[C_SZ * C_SZ], g_wol[C_SZ * C_SZ];    // Wo^T fp16 limbs

// ---------------------------------------------------------------------------
#define CP_ASYNC16(dst, src) \
    asm volatile("cp.async.cg.shared.global [%0], [%1], 16;\n" :: "r"(dst), "l"(src))

__device__ __forceinline__ unsigned cvt_tf32(float f) {
    unsigned u;
    asm("cvt.rna.tf32.f32 %0, %1;" : "=r"(u) : "f"(f));
    return u;
}

__device__ __forceinline__ uint32_t smem_u32(const void* p) {
    uint32_t a;
    asm("{ .reg .u64 t; cvta.to.shared.u64 t, %1; cvt.u32.u64 %0, t; }" : "=r"(a) : "l"(p));
    return a;
}

#define MMA_TF32(d, a, b) \
    asm volatile("mma.sync.aligned.m16n8k8.row.col.f32.tf32.tf32.f32 " \
                 "{%0,%1,%2,%3}, {%4,%5,%6,%7}, {%8,%9}, {%0,%1,%2,%3};\n" \
                 : "+f"(d[0]), "+f"(d[1]), "+f"(d[2]), "+f"(d[3]) \
                 : "r"(a[0]), "r"(a[1]), "r"(a[2]), "r"(a[3]), "r"(b[0]), "r"(b[1]))

#define MMA_F16(d, a, b) \
    asm volatile("mma.sync.aligned.m16n8k16.row.col.f32.f16.f16.f32 " \
                 "{%0,%1,%2,%3}, {%4,%5,%6,%7}, {%8,%9}, {%0,%1,%2,%3};\n" \
                 : "+f"(d[0]), "+f"(d[1]), "+f"(d[2]), "+f"(d[3]) \
                 : "r"(a[0]), "r"(a[1]), "r"(a[2]), "r"(a[3]), "r"(b[0]), "r"(b[1]))

#define LDSM_X4(r0, r1, r2, r3, addr) \
    asm volatile("ldmatrix.sync.aligned.m8n8.x4.shared.b16 {%0,%1,%2,%3}, [%4];" \
                 : "=r"(r0), "=r"(r1), "=r"(r2), "=r"(r3) : "r"(addr))

// ---------------------------------------------------------------------------
// Elementwise fp32 -> fp16 (single plane)
// ---------------------------------------------------------------------------
__global__ void cvt16_kernel(const float* __restrict__ x, fp16* __restrict__ o, int n) {
    int i = blockIdx.x * blockDim.x + threadIdx.x;
    if (i >= n) return;
    o[i] = __float2half_rn(x[i]);
}

// ---------------------------------------------------------------------------
// Transpose + fp16 hi/lo split, fused QKV weights: -> limbs [3072][2048]
// ---------------------------------------------------------------------------
__global__ void tsplit_qkv(const float* __restrict__ Wq, const float* __restrict__ Wk,
                           const float* __restrict__ Wv, fp16* __restrict__ hi,
                           fp16* __restrict__ lo) {
    __shared__ float s[32][33];
    int tx = threadIdx.x, ty = threadIdx.y;     // 32 x 8
    int bx = blockIdx.x, gk = blockIdx.y * 32;
    const float* W;
    int N, nb, obase;
    if (bx < 64)      { W = Wq; N = 2048; nb = bx;      obase = 0; }
    else if (bx < 80) { W = Wk; N = 512;  nb = bx - 64; obase = 2048; }
    else              { W = Wv; N = 512;  nb = bx - 80; obase = 2560; }
    int gn = nb * 32;
#pragma unroll
    for (int j = 0; j < 4; j++)
        s[ty + j * 8][tx] = W[(size_t)(gk + ty + j * 8) * N + gn + tx];
    __syncthreads();
#pragma unroll
    for (int j = 0; j < 4; j++) {
        float v = s[tx][ty + j * 8];
        fp16 h = __float2half_rn(v);
        size_t o = (size_t)(obase + gn + ty + j * 8) * C_SZ + gk + tx;
        hi[o] = h;
        lo[o] = __float2half_rn(v - __half2float(h));
    }
}

// Transpose + split single weight Wo [K][N] -> [N][K]
__global__ void tsplit_kernel(const float* __restrict__ W, fp16* __restrict__ hi,
                              fp16* __restrict__ lo, int K, int N) {
    __shared__ float s[32][33];
    int tx = threadIdx.x, ty = threadIdx.y;     // 32 x 8
    int gn = blockIdx.x * 32, gk = blockIdx.y * 32;
#pragma unroll
    for (int j = 0; j < 4; j++)
        s[ty + j * 8][tx] = W[(size_t)(gk + ty + j * 8) * N + gn + tx];
    __syncthreads();
#pragma unroll
    for (int j = 0; j < 4; j++) {
        float v = s[tx][ty + j * 8];
        fp16 h = __float2half_rn(v);
        size_t o = (size_t)(gn + ty + j * 8) * K + gk + tx;
        hi[o] = h;
        lo[o] = __float2half_rn(v - __half2float(h));
    }
}

// ---------------------------------------------------------------------------
// fp16 2-product GEMM: C[M,N] = A[M,K] @ (Bh + Bl)[N,K]^T
// A single fp16 plane; B split into fp16 hi/lo limbs (weights, near-exact).
// Block 128x128x32, 256 threads, warp 64x32, m16n8k16 f16, 2-stage cp.async,
// 2 CTAs/SM, ldmatrix.x4 loads. 32 MMAs per ks (vs 48 in bf16x3).
// ---------------------------------------------------------------------------
#define BBM 128
#define BBN 128
#define BBK 32
#define KSTR 40
#define BPLANE (128 * KSTR)          // fp16 elems per plane (5120)
#define PLANE_B 10240                // bytes per plane
#define STAGE_B 30720                // bytes per stage (3 planes)

__global__ __launch_bounds__(256, 2) void gemm_f2(const fp16* __restrict__ A,
                                                  const fp16* __restrict__ Bh,
                                                  const fp16* __restrict__ Bl,
                                                  float* __restrict__ C,
                                                  int M, int N, int K) {
    extern __shared__ fp16 smb[];

    int tid = threadIdx.x;
    int warp = tid >> 5, lane = tid & 31;
    int g = lane >> 2, tg = lane & 3;
    int wm = (warp & 1) * 64;
    int wn = (warp >> 1) * 32;
    int brow = blockIdx.y * BBM, bcol = blockIdx.x * BBN;

    float acc[4][4][4] = {};
    const int nK = K / BBK;

    uint32_t sbase = smem_u32(smb);
    uint32_t a_lane = (uint32_t)(wm + (lane & 15)) * 80u + ((lane >> 4) & 1) * 16u;
    uint32_t b_lane = (uint32_t)(wn + ((lane >> 4) * 8) + (lane & 7)) * 80u
                    + ((lane >> 3) & 1) * 16u;

    auto loadTile = [&](int kt, int buf) {
        fp16* dstb = smb + buf * (3 * BPLANE);
#pragma unroll
        for (int i = 0; i < 6; i++) {
            int idx = tid + i * 256;
            int plane = idx >> 9;        // 0=A, 1=Bh, 2=Bl
            int rem = idx & 511;
            int row = rem >> 2, c = rem & 3;
            const fp16* src;
            if (plane == 0)      src = A + (size_t)(brow + row) * K;
            else if (plane == 1) src = Bh + (size_t)(bcol + row) * K;
            else                 src = Bl + (size_t)(bcol + row) * K;
            src += kt * BBK + c * 8;
            unsigned d = smem_u32(dstb + plane * BPLANE + row * KSTR + c * 8);
            CP_ASYNC16(d, src);
        }
        asm volatile("cp.async.commit_group;\n");
    };

    loadTile(0, 0);

    for (int kt = 0; kt < nK; kt++) {
        if (kt + 1 < nK) {
            loadTile(kt + 1, (kt + 1) & 1);
            asm volatile("cp.async.wait_group 1;\n");
        } else {
            asm volatile("cp.async.wait_group 0;\n");
        }
        __syncthreads();

        uint32_t stg = sbase + (kt & 1) * STAGE_B;
        uint32_t aA  = stg + a_lane;
        uint32_t aBh = stg + PLANE_B + b_lane;
        uint32_t aBl = aBh + PLANE_B;

#pragma unroll
        for (int ks = 0; ks < 2; ks++) {
            uint32_t kb = ks * 32u;
            unsigned Af[4][4], Bfh[4][2], Bfl[4][2];
#pragma unroll
            for (int mt = 0; mt < 4; mt++)
                LDSM_X4(Af[mt][0], Af[mt][1], Af[mt][2], Af[mt][3],
                        aA + mt * (16u * 80u) + kb);
#pragma unroll
            for (int p = 0; p < 2; p++) {
                LDSM_X4(Bfh[2 * p][0], Bfh[2 * p][1], Bfh[2 * p + 1][0], Bfh[2 * p + 1][1],
                        aBh + p * (16u * 80u) + kb);
                LDSM_X4(Bfl[2 * p][0], Bfl[2 * p][1], Bfl[2 * p + 1][0], Bfl[2 * p + 1][1],
                        aBl + p * (16u * 80u) + kb);
            }
            // product-first: A*Bh pass then A*Bl pass (per-acc order hi->lo)
#pragma unroll
            for (int mt = 0; mt < 4; mt++)
#pragma unroll
                for (int nt = 0; nt < 4; nt++)
                    MMA_F16(acc[mt][nt], Af[mt], Bfh[nt]);
#pragma unroll
            for (int mt = 0; mt < 4; mt++)
#pragma unroll
                for (int nt = 0; nt < 4; nt++)
                    MMA_F16(acc[mt][nt], Af[mt], Bfl[nt]);
        }
        __syncthreads();
    }

#pragma unroll
    for (int mt = 0; mt < 4; mt++) {
        int r0 = brow + wm + mt * 16 + g;
#pragma unroll
        for (int nt = 0; nt < 4; nt++) {
            int c0 = bcol + wn + nt * 8 + tg * 2;
            *(float2*)&C[(size_t)r0 * N + c0] = make_float2(acc[mt][nt][0], acc[mt][nt][1]);
            *(float2*)&C[(size_t)(r0 + 8) * N + c0] = make_float2(acc[mt][nt][2], acc[mt][nt][3]);
        }
    }
}

// ---------------------------------------------------------------------------
// Fused RoPE + tf32-rna rounding over packed QKV.
// 48 slots: 0-31 q rope (fp32), 32-39 k rope+rna, 40-47 v rna only.
// ---------------------------------------------------------------------------
__global__ void rope_fused(float* __restrict__ qkv) {
    int idx = blockIdx.x * blockDim.x + threadIdx.x;
    int total = ROWS * 48 * 32;
    if (idx >= total) return;
    int i = idx & 31;
    int hh = (idx >> 5) % 48;
    int row = idx / (48 * 32);

    float* p;
    if (hh < 32)      p = qkv + (size_t)row * QKVLD + hh * HD;
    else if (hh < 40) p = qkv + (size_t)row * QKVLD + 2048 + (hh - 32) * HD;
    else              p = qkv + (size_t)row * QKVLD + 2560 + (hh - 40) * HD;

    if (hh >= 40) {   // v: tf32-rna round only
        p[i]      = __uint_as_float(cvt_tf32(p[i]));
        p[i + 32] = __uint_as_float(cvt_tf32(p[i + 32]));
        return;
    }

    int t = row & (T_SZ - 1);
    float invf = expf(-(float)i * 0.28782313662425574f);  // ln(10000)/32
    float ang = (float)t * invf;
    float c = cosf(ang), s = sinf(ang);

    float x0 = p[i];
    float x1 = p[i + 32];
    float r0 = x0 * c - x1 * s;
    float r1 = x1 * c + x0 * s;
    if (hh >= 32) {   // k: rope + rna round
        p[i]      = __uint_as_float(cvt_tf32(r0));
        p[i + 32] = __uint_as_float(cvt_tf32(r1));
    } else {          // q: rope, fp32
        p[i]      = r0;
        p[i + 32] = r1;
    }
}

// ---------------------------------------------------------------------------
// TF32 tensor-core flash attention (causal), fused-QKV input (stride 3072).
// Epilogue writes y directly as a single fp16 plane (feeds fp16 Wo GEMM).
// ---------------------------------------------------------------------------
#define FQ 128
#define FK 64
#define FSTR 68
#define FBUF (FK * FSTR * 2)

__global__ __launch_bounds__(256, 2) void flash_tc(const float* __restrict__ qkv,
                                                   fp16* __restrict__ y16) {
    extern __shared__ float smf[];
    int qt = blockIdx.x, h = blockIdx.y, b = blockIdx.z;
    int hk = h >> 2;
    int tid = threadIdx.x, w = tid >> 5, lane = tid & 31;
    int g = lane >> 2, tg = lane & 3;
    int qbase = qt * FQ;
    size_t bT = (size_t)b * T_SZ;

    {
        const float* qg = qkv + (bT + qbase) * QKVLD + h * HD;
#pragma unroll
        for (int i = 0; i < 8; i++) {
            int idx = tid + i * 256;
            int r = idx >> 4, c4 = (idx & 15) * 4;
            unsigned d = smem_u32(smf + r * FSTR + c4);
            CP_ASYNC16(d, qg + (size_t)r * QKVLD + c4);
        }
        asm volatile("cp.async.commit_group;\ncp.async.wait_group 0;\n");
    }
    __syncthreads();

    unsigned qa[8][4];
    {
        int r0 = w * 16 + g;
#pragma unroll
        for (int c = 0; c < 8; c++) {
            qa[c][0] = cvt_tf32(smf[r0 * FSTR + 8 * c + tg] * 0.125f);
            qa[c][1] = cvt_tf32(smf[(r0 + 8) * FSTR + 8 * c + tg] * 0.125f);
            qa[c][2] = cvt_tf32(smf[r0 * FSTR + 8 * c + tg + 4] * 0.125f);
            qa[c][3] = cvt_tf32(smf[(r0 + 8) * FSTR + 8 * c + tg + 4] * 0.125f);
        }
    }
    __syncthreads();

    auto loadKV = [&](int kt, int buf) {
        float* base = smf + buf * FBUF;
        const float* kg = qkv + (bT + kt * FK) * QKVLD + 2048 + hk * HD;
        const float* vg = qkv + (bT + kt * FK) * QKVLD + 2560 + hk * HD;
#pragma unroll
        for (int i = 0; i < 4; i++) {
            int idx = tid + i * 256;
            int r = idx >> 4, c4 = (idx & 15) * 4;
            unsigned dk = smem_u32(base + r * FSTR + c4);
            CP_ASYNC16(dk, kg + (size_t)r * QKVLD + c4);
            unsigned dv = smem_u32(base + FK * FSTR + r * FSTR + c4);
            CP_ASYNC16(dv, vg + (size_t)r * QKVLD + c4);
        }
        asm volatile("cp.async.commit_group;\n");
    };

    float yacc[8][4] = {};
    float m0 = -INFINITY, m1 = -INFINITY, l0 = 0.0f, l1 = 0.0f;
    int rg0 = qbase + w * 16 + g;

    int nkt = 2 * qt + 2;
    loadKV(0, 0);

    for (int kt = 0; kt < nkt; kt++) {
        if (kt + 1 < nkt) {
            loadKV(kt + 1, (kt + 1) & 1);
            asm volatile("cp.async.wait_group 1;\n");
        } else {
            asm volatile("cp.async.wait_group 0;\n");
        }
        __syncthreads();

        bool active = (FK * kt <= qbase + 16 * w + 15);
        if (active) {
            const float* Ks = smf + (kt & 1) * FBUF;
            const float* Vs = Ks + FK * FSTR;

            float sacc[8][4] = {};
#pragma unroll
            for (int c = 0; c < 8; c++) {
#pragma unroll
                for (int nf = 0; nf < 8; nf++) {
                    unsigned bb[2];
                    bb[0] = __float_as_uint(Ks[(8 * nf + g) * FSTR + 8 * c + tg]);
                    bb[1] = __float_as_uint(Ks[(8 * nf + g) * FSTR + 8 * c + tg + 4]);
                    MMA_TF32(sacc[nf], qa[c], bb);
                }
            }

            if (kt >= 2 * qt) {
                int k0 = FK * kt;
#pragma unroll
                for (int nf = 0; nf < 8; nf++) {
                    int jg = k0 + 8 * nf + 2 * tg;
                    if (jg > rg0)     sacc[nf][0] = -INFINITY;
                    if (jg + 1 > rg0) sacc[nf][1] = -INFINITY;
                    if (jg > rg0 + 8)     sacc[nf][2] = -INFINITY;
                    if (jg + 1 > rg0 + 8) sacc[nf][3] = -INFINITY;
                }
            }

            float mt0 = -INFINITY, mt1 = -INFINITY;
#pragma unroll
            for (int nf = 0; nf < 8; nf++) {
                mt0 = fmaxf(mt0, fmaxf(sacc[nf][0], sacc[nf][1]));
                mt1 = fmaxf(mt1, fmaxf(sacc[nf][2], sacc[nf][3]));
            }
            mt0 = fmaxf(mt0, __shfl_xor_sync(0xffffffffu, mt0, 1));
            mt0 = fmaxf(mt0, __shfl_xor_sync(0xffffffffu, mt0, 2));
            mt1 = fmaxf(mt1, __shfl_xor_sync(0xffffffffu, mt1, 1));
            mt1 = fmaxf(mt1, __shfl_xor_sync(0xffffffffu, mt1, 2));

            float mn0 = fmaxf(m0, mt0), mn1 = fmaxf(m1, mt1);
            float al0 = __expf(m0 - mn0), al1 = __expf(m1 - mn1);
            m0 = mn0; m1 = mn1;
#pragma unroll
            for (int nf = 0; nf < 8; nf++) {
                yacc[nf][0] *= al0; yacc[nf][1] *= al0;
                yacc[nf][2] *= al1; yacc[nf][3] *= al1;
            }

            float pl0 = 0.0f, pl1 = 0.0f;
#pragma unroll
            for (int c = 0; c < 8; c++) {
                float p0 = __expf(sacc[c][0] - mn0);
                float p1 = __expf(sacc[c][1] - mn0);
                float p2 = __expf(sacc[c][2] - mn1);
                float p3 = __expf(sacc[c][3] - mn1);
                pl0 += p0 + p1;
                pl1 += p2 + p3;
                unsigned pa[4];
                pa[0] = cvt_tf32(p0);
                pa[1] = cvt_tf32(p2);
                pa[2] = cvt_tf32(p1);
                pa[3] = cvt_tf32(p3);
#pragma unroll
                for (int nf = 0; nf < 8; nf++) {
                    unsigned bb[2];
                    bb[0] = __float_as_uint(Vs[(8 * c + 2 * tg) * FSTR + 8 * nf + g]);
                    bb[1] = __float_as_uint(Vs[(8 * c + 2 * tg + 1) * FSTR + 8 * nf + g]);
                    MMA_TF32(yacc[nf], pa, bb);
                }
            }
            pl0 += __shfl_xor_sync(0xffffffffu, pl0, 1);
            pl0 += __shfl_xor_sync(0xffffffffu, pl0, 2);
            pl1 += __shfl_xor_sync(0xffffffffu, pl1, 1);
            pl1 += __shfl_xor_sync(0xffffffffu, pl1, 2);
            l0 = l0 * al0 + pl0;
            l1 = l1 * al1 + pl1;
        }
        __syncthreads();
    }

    // normalize + store as single fp16 plane
    float inv0 = 1.0f / l0, inv1 = 1.0f / l1;
    size_t r0 = (bT + qbase + w * 16 + g) * C_SZ + h * HD;
    size_t r1 = r0 + 8 * (size_t)C_SZ;
#pragma unroll
    for (int nf = 0; nf < 8; nf++) {
        int c0 = 8 * nf + 2 * tg;
        *(__half2*)&y16[r0 + c0] = __floats2half2_rn(yacc[nf][0] * inv0, yacc[nf][1] * inv0);
        *(__half2*)&y16[r1 + c0] = __floats2half2_rn(yacc[nf][2] * inv1, yacc[nf][3] * inv1);
    }
}

// ---------------------------------------------------------------------------
extern "C" void kernel_launch(void* const* d_in, const int* in_sizes, int n_in,
                              void* d_out, int out_size) {
    const float* x  = (const float*)d_in[0];
    const float* Wq = (const float*)d_in[1];
    const float* Wk = (const float*)d_in[2];
    const float* Wv = (const float*)d_in[3];
    const float* Wo = (const float*)d_in[4];
    float* out = (float*)d_out;

    float* pqkv;
    cudaGetSymbolAddress((void**)&pqkv, g_qkv);

    fp16 *x16, *y16, *wh, *wl, *woh, *wol;
    cudaGetSymbolAddress((void**)&x16, g_x16);
    cudaGetSymbolAddress((void**)&y16, g_y16);
    cudaGetSymbolAddress((void**)&wh, g_wh);  cudaGetSymbolAddress((void**)&wl, g_wl);
    cudaGetSymbolAddress((void**)&woh, g_woh); cudaGetSymbolAddress((void**)&wol, g_wol);

    int bsmem = 2 * STAGE_B;                          // 61440
    cudaFuncSetAttribute(gemm_f2, cudaFuncAttributeMaxDynamicSharedMemorySize, bsmem);
    int fsmem = 2 * FBUF * (int)sizeof(float);        // 69632
    cudaFuncSetAttribute(flash_tc, cudaFuncAttributeMaxDynamicSharedMemorySize, fsmem);

    // (0) x -> fp16; (1) fused QKV weight limbs; (2) Wo limbs
    {
        int n = ROWS * C_SZ;
        cvt16_kernel<<<(n + 255) / 256, 256>>>(x, x16, n);
    }
    tsplit_qkv<<<dim3(96, C_SZ / 32), dim3(32, 8)>>>(Wq, Wk, Wv, wh, wl);
    tsplit_kernel<<<dim3(C_SZ / 32, C_SZ / 32), dim3(32, 8)>>>(Wo, woh, wol, C_SZ, C_SZ);

    // (3) fused QKV projection (fp16 2-product)
    gemm_f2<<<dim3(QKVLD / BBN, ROWS / BBM), 256, bsmem>>>(
        x16, wh, wl, pqkv, ROWS, QKVLD, C_SZ);

    // (4) fused RoPE + k/v tf32-rna rounding
    {
        int tot = ROWS * 48 * 32;
        rope_fused<<<(tot + 255) / 256, 256>>>(pqkv);
    }

    // (5) flash attention (tf32) -> y fp16 plane   <- ncu slot (-s 5)
    flash_tc<<<dim3(T_SZ / FQ, NH, B_SZ), 256, fsmem>>>(pqkv, y16);

    // (6) output projection (fp16 2-product)
    gemm_f2<<<dim3(C_SZ / BBN, ROWS / BBM), 256, bsmem>>>(
        y16, woh, wol, out, ROWS, C_SZ, C_SZ);
}